// round 2
// baseline (speedup 1.0000x reference)
#include <cuda_runtime.h>
#include <math.h>

#define BATCH  2
#define SEQ    2048
#define DMODEL 4096
#define NHEADS 32
#define NKV    8
#define HDIM   128
#define MROWS  (BATCH*SEQ)        // 4096
#define KVW    (NKV*HDIM)         // 1024

// ---------------- scratch (static device allocations; no cudaMalloc) -------
__device__ float g_rawQ[(size_t)MROWS * DMODEL];   // x@Wq, row-major [M, 4096]
__device__ float g_rawK[(size_t)MROWS * KVW];      // x@Wk, row-major [M, 1024]
__device__ float g_rawV[(size_t)MROWS * KVW];      // x@Wv, row-major [M, 1024]
__device__ float g_Q[(size_t)MROWS * DMODEL];      // roped, [B,H,S,HD]
__device__ float g_K[(size_t)MROWS * KVW];         // roped, [B,KV,S,HD]
__device__ float g_O[(size_t)MROWS * DMODEL];      // attn out, [B,S,H*HD] = [M, 4096]

// ---------------- SGEMM: C[M,N] = A[M,K] @ W[K,N], row-major ---------------
// 128x128 block tile, BK=16, 256 threads, 8x8 per-thread tile.
// Thread (tx,ty): rows ty*8+i, cols tx+16*j  (strided cols -> conflict-free Ws reads)
__global__ __launch_bounds__(256) void sgemm_kernel(
    const float* __restrict__ A, const float* __restrict__ W,
    float* __restrict__ C, int M, int N, int K)
{
    __shared__ float As[16][128];   // transposed A tile: As[k][m]
    __shared__ float Ws[16][128];   // Ws[k][n]
    const int tid = threadIdx.x;
    const int tx = tid & 15, ty = tid >> 4;
    const int bx = blockIdx.x, by = blockIdx.y;
    const float* Ablk = A + (size_t)by * 128 * K;
    const float* Wblk = W + (size_t)bx * 128;

    float acc[8][8];
#pragma unroll
    for (int i = 0; i < 8; i++)
#pragma unroll
        for (int j = 0; j < 8; j++) acc[i][j] = 0.f;

    for (int k0 = 0; k0 < K; k0 += 16) {
        // load A tile 128x16 (2 float4 per thread), store transposed
#pragma unroll
        for (int l = 0; l < 2; l++) {
            int id = tid + l * 256;
            int r  = id >> 2;              // 0..127
            int c4 = (id & 3) << 2;        // 0,4,8,12
            float4 v = *reinterpret_cast<const float4*>(Ablk + (size_t)r * K + k0 + c4);
            As[c4 + 0][r] = v.x; As[c4 + 1][r] = v.y;
            As[c4 + 2][r] = v.z; As[c4 + 3][r] = v.w;
        }
        // load W tile 16x128
#pragma unroll
        for (int l = 0; l < 2; l++) {
            int id = tid + l * 256;
            int r  = id >> 5;              // 0..15
            int c4 = (id & 31) << 2;       // 0..124
            *reinterpret_cast<float4*>(&Ws[r][c4]) =
                *reinterpret_cast<const float4*>(Wblk + (size_t)(k0 + r) * N + c4);
        }
        __syncthreads();
#pragma unroll
        for (int kk = 0; kk < 16; kk++) {
            float ra[8], rb[8];
#pragma unroll
            for (int i = 0; i < 8; i++) ra[i] = As[kk][ty * 8 + i];
#pragma unroll
            for (int j = 0; j < 8; j++) rb[j] = Ws[kk][tx + 16 * j];
#pragma unroll
            for (int i = 0; i < 8; i++)
#pragma unroll
                for (int j = 0; j < 8; j++) acc[i][j] += ra[i] * rb[j];
        }
        __syncthreads();
    }
#pragma unroll
    for (int i = 0; i < 8; i++) {
        size_t row = (size_t)(by * 128 + ty * 8 + i) * N + bx * 128;
#pragma unroll
        for (int j = 0; j < 8; j++) C[row + tx + 16 * j] = acc[i][j];
    }
}

// ---------------- RoPE + head-major relayout -------------------------------
// raw: [B, S, nheads*128] row-major -> out: [B, nheads, S, 128] with RoPE
__global__ __launch_bounds__(256) void rope_kernel(
    const float* __restrict__ raw, float* __restrict__ out, int nheads)
{
    int idx = blockIdx.x * blockDim.x + threadIdx.x;       // B*nheads*S*64 threads
    int d2 = idx & 63;
    int t  = idx >> 6;
    int s  = t & (SEQ - 1);
    t >>= 11;
    int h = t % nheads;
    int b = t / nheads;
    if (b >= BATCH) return;

    const float* row = raw + ((size_t)(b * SEQ + s)) * (nheads * HDIM) + h * HDIM;
    float x0 = row[d2], x1 = row[d2 + 64];
    // match reference: fp32 inv_freq, fp32 angle, accurate sin/cos of that angle
    float invf = expf(-(float)d2 * (9.210340371976184f / 64.0f));  // 10000^(-d2/64)
    float ang  = (float)s * invf;
    double sv, cv;
    sincos((double)ang, &sv, &cv);
    float c = (float)cv, sn = (float)sv;
    float o0 = x0 * c - x1 * sn;    // rotate_half: [0:64] gets -x[64:128]
    float o1 = x1 * c + x0 * sn;    // [64:128] gets +x[0:64]
    float* orow = out + ((size_t)((b * nheads + h) * SEQ + s)) * HDIM;
    orow[d2]      = o0;
    orow[d2 + 64] = o1;
}

// ---------------- Flash attention (fp32, causal, online softmax) -----------
// grid: (S/64, B*NHEADS), 256 threads (16x16).
// Thread (tx,ty): score tile rows ty*4+r, key cols tx+16*cc; out cols tx+16*c.
// Smem padded (stride 129 / 65) for conflict-free compute-phase LDS.
#define FLASH_SMEM_FLOATS (3 * 64 * 129 + 64 * 65)
__global__ __launch_bounds__(256) void flash_kernel(
    const float* __restrict__ Q, const float* __restrict__ K,
    const float* __restrict__ Vraw, float* __restrict__ O)
{
    extern __shared__ float sm[];
    float* Qs = sm;                 // [64][129]
    float* Ks = Qs + 64 * 129;      // [64][129]
    float* Vs = Ks + 64 * 129;      // [64][129]
    float* Ps = Vs + 64 * 129;      // [64][65]

    const int tid = threadIdx.x;
    const int tx = tid & 15, ty = tid >> 4;
    const int m0 = blockIdx.x * 64;
    const int bh = blockIdx.y;
    const int b = bh >> 5, h = bh & 31;
    const int kv = h >> 2;                       // GROUP = 4
    const float scale = 0.08838834764831845f;    // 128^-0.5

    const float* Qbase = Q + ((size_t)(b * NHEADS + h) * SEQ + m0) * HDIM;
    const float* Kbase = K + (size_t)(b * NKV + kv) * SEQ * HDIM;
    const float* Vbase = Vraw + (size_t)b * SEQ * KVW + kv * HDIM;  // row stride KVW

    // load Q block [64,128] -> padded smem
    for (int i = tid; i < 64 * 32; i += 256) {
        int r = i >> 5, c4 = (i & 31) << 2;
        float4 v = *reinterpret_cast<const float4*>(Qbase + (size_t)r * HDIM + c4);
        float* d = &Qs[r * 129 + c4];
        d[0] = v.x; d[1] = v.y; d[2] = v.z; d[3] = v.w;
    }

    float acc[4][8];
#pragma unroll
    for (int r = 0; r < 4; r++)
#pragma unroll
        for (int c = 0; c < 8; c++) acc[r][c] = 0.f;
    float mi[4] = {-INFINITY, -INFINITY, -INFINITY, -INFINITY};
    float li[4] = {0.f, 0.f, 0.f, 0.f};

    const int nb = blockIdx.x + 1;  // causal: key blocks 0..blockIdx.x
    for (int kb = 0; kb < nb; kb++) {
        const int n0 = kb * 64;
        __syncthreads();  // protect Qs (1st iter) + Ks/Vs reuse (later iters)
        for (int i = tid; i < 64 * 32; i += 256) {
            int r = i >> 5, c4 = (i & 31) << 2;
            float4 v = *reinterpret_cast<const float4*>(Kbase + (size_t)(n0 + r) * HDIM + c4);
            float* d = &Ks[r * 129 + c4];
            d[0] = v.x; d[1] = v.y; d[2] = v.z; d[3] = v.w;
            float4 w = *reinterpret_cast<const float4*>(Vbase + (size_t)(n0 + r) * KVW + c4);
            float* e = &Vs[r * 129 + c4];
            e[0] = w.x; e[1] = w.y; e[2] = w.z; e[3] = w.w;
        }
        __syncthreads();

        // scores s[r][cc] = Q[ty*4+r] . K[tx+16cc]
        float s[4][4];
#pragma unroll
        for (int r = 0; r < 4; r++)
#pragma unroll
            for (int c = 0; c < 4; c++) s[r][c] = 0.f;
#pragma unroll 4
        for (int d = 0; d < 128; d++) {
            float qa[4], ka[4];
#pragma unroll
            for (int r = 0; r < 4; r++) qa[r] = Qs[(ty * 4 + r) * 129 + d];
#pragma unroll
            for (int c = 0; c < 4; c++) ka[c] = Ks[(tx + 16 * c) * 129 + d];
#pragma unroll
            for (int r = 0; r < 4; r++)
#pragma unroll
                for (int c = 0; c < 4; c++) s[r][c] += qa[r] * ka[c];
        }

        // scale + causal mask + online softmax
#pragma unroll
        for (int r = 0; r < 4; r++) {
            const int qi = m0 + ty * 4 + r;
            float mx = -INFINITY;
#pragma unroll
            for (int c = 0; c < 4; c++) {
                int kj = n0 + tx + 16 * c;
                s[r][c] = (kj <= qi) ? s[r][c] * scale : -INFINITY;
                mx = fmaxf(mx, s[r][c]);
            }
#pragma unroll
            for (int o = 8; o; o >>= 1) mx = fmaxf(mx, __shfl_xor_sync(0xffffffffu, mx, o));
            float mtot  = fmaxf(mi[r], mx);
            float alpha = __expf(mi[r] - mtot);
            mi[r] = mtot;
            float lsum = 0.f;
#pragma unroll
            for (int c = 0; c < 4; c++) {
                float p = __expf(s[r][c] - mtot);
                s[r][c] = p;
                lsum += p;
            }
#pragma unroll
            for (int o = 8; o; o >>= 1) lsum += __shfl_xor_sync(0xffffffffu, lsum, o);
            li[r] = li[r] * alpha + lsum;
#pragma unroll
            for (int c = 0; c < 8; c++) acc[r][c] *= alpha;
#pragma unroll
            for (int c = 0; c < 4; c++) Ps[(ty * 4 + r) * 65 + tx + 16 * c] = s[r][c];
        }
        __syncwarp();   // Ps row producers == consumers within the same warp

        // acc += P @ V
#pragma unroll 2
        for (int kj = 0; kj < 64; kj++) {
            float pv[4], vv[8];
#pragma unroll
            for (int r = 0; r < 4; r++) pv[r] = Ps[(ty * 4 + r) * 65 + kj];
#pragma unroll
            for (int c = 0; c < 8; c++) vv[c] = Vs[kj * 129 + tx + 16 * c];
#pragma unroll
            for (int r = 0; r < 4; r++)
#pragma unroll
                for (int c = 0; c < 8; c++) acc[r][c] += pv[r] * vv[c];
        }
    }

    // epilogue: normalize + write O[b, s, h*128 + col]
#pragma unroll
    for (int r = 0; r < 4; r++) {
        float inv = 1.f / li[r];
        int qi = m0 + ty * 4 + r;
        float* orow = O + ((size_t)(b * SEQ + qi)) * DMODEL + h * HDIM;
#pragma unroll
        for (int c = 0; c < 8; c++) orow[tx + 16 * c] = acc[r][c] * inv;
    }
}

// ---------------- launch ----------------------------------------------------
extern "C" void kernel_launch(void* const* d_in, const int* in_sizes, int n_in,
                              void* d_out, int out_size)
{
    (void)in_sizes; (void)n_in; (void)out_size;
    const float* x  = (const float*)d_in[0];
    // d_in[1] = mask (causal triu) -- deterministic, handled in-kernel
    const float* Wq = (const float*)d_in[2];
    const float* Wk = (const float*)d_in[3];
    const float* Wv = (const float*)d_in[4];
    const float* Wo = (const float*)d_in[5];
    float* out = (float*)d_out;

    float *rawQ, *rawK, *rawV, *Qr, *Kr, *Ob;
    cudaGetSymbolAddress((void**)&rawQ, g_rawQ);
    cudaGetSymbolAddress((void**)&rawK, g_rawK);
    cudaGetSymbolAddress((void**)&rawV, g_rawV);
    cudaGetSymbolAddress((void**)&Qr,   g_Q);
    cudaGetSymbolAddress((void**)&Kr,   g_K);
    cudaGetSymbolAddress((void**)&Ob,   g_O);

    const int flash_smem = FLASH_SMEM_FLOATS * (int)sizeof(float);   // ~113 KB
    cudaFuncSetAttribute(flash_kernel, cudaFuncAttributeMaxDynamicSharedMemorySize,
                         flash_smem);

    // QKV projections
    sgemm_kernel<<<dim3(DMODEL / 128, MROWS / 128), 256>>>(x, Wq, rawQ, MROWS, DMODEL, DMODEL);
    sgemm_kernel<<<dim3(KVW   / 128, MROWS / 128), 256>>>(x, Wk, rawK, MROWS, KVW,    DMODEL);
    sgemm_kernel<<<dim3(KVW   / 128, MROWS / 128), 256>>>(x, Wv, rawV, MROWS, KVW,    DMODEL);

    // RoPE + relayout
    rope_kernel<<<(BATCH * NHEADS * SEQ * 64) / 256, 256>>>(rawQ, Qr, NHEADS);
    rope_kernel<<<(BATCH * NKV    * SEQ * 64) / 256, 256>>>(rawK, Kr, NKV);

    // causal flash attention (V read directly from raw [B,S,KV*128] layout)
    flash_kernel<<<dim3(SEQ / 64, BATCH * NHEADS), 256, flash_smem>>>(Qr, Kr, rawV, Ob);

    // output projection
    sgemm_kernel<<<dim3(DMODEL / 128, MROWS / 128), 256>>>(Ob, Wo, out, MROWS, DMODEL, DMODEL);
}

// round 4
// speedup vs baseline: 3.3538x; 3.3538x over previous
#include <cuda_runtime.h>
#include <cuda_bf16.h>
#include <math.h>
#include <stdint.h>

#define BATCH  2
#define SEQ    2048
#define DMODEL 4096
#define NHEADS 32
#define NKV    8
#define HDIM   128
#define MROWS  (BATCH*SEQ)        // 4096
#define KVW    (NKV*HDIM)         // 1024

// ---------------- scratch (static device buffers; no cudaMalloc) -----------
__device__ __align__(256) float g_rawQ[(size_t)MROWS * DMODEL];
__device__ __align__(256) float g_rawK[(size_t)MROWS * KVW];
__device__ __align__(256) float g_rawV[(size_t)MROWS * KVW];
__device__ __align__(256) float g_Q[(size_t)MROWS * DMODEL];
__device__ __align__(256) float g_K[(size_t)MROWS * KVW];
__device__ __align__(256) float g_O[(size_t)MROWS * DMODEL];

// split-bf16 operands
__device__ __align__(256) __nv_bfloat16 g_xhi[(size_t)MROWS * DMODEL];
__device__ __align__(256) __nv_bfloat16 g_xlo[(size_t)MROWS * DMODEL];
__device__ __align__(256) __nv_bfloat16 g_Ohi[(size_t)MROWS * DMODEL];
__device__ __align__(256) __nv_bfloat16 g_Olo[(size_t)MROWS * DMODEL];
// transposed weights [N, K] bf16 hi/lo
__device__ __align__(256) __nv_bfloat16 g_Wqt_h[(size_t)DMODEL * DMODEL];
__device__ __align__(256) __nv_bfloat16 g_Wqt_l[(size_t)DMODEL * DMODEL];
__device__ __align__(256) __nv_bfloat16 g_Wkt_h[(size_t)KVW * DMODEL];
__device__ __align__(256) __nv_bfloat16 g_Wkt_l[(size_t)KVW * DMODEL];
__device__ __align__(256) __nv_bfloat16 g_Wvt_h[(size_t)KVW * DMODEL];
__device__ __align__(256) __nv_bfloat16 g_Wvt_l[(size_t)KVW * DMODEL];
__device__ __align__(256) __nv_bfloat16 g_Wot_h[(size_t)DMODEL * DMODEL];
__device__ __align__(256) __nv_bfloat16 g_Wot_l[(size_t)DMODEL * DMODEL];
// RoPE tables
__device__ __align__(256) float g_cosT[SEQ * 64];
__device__ __align__(256) float g_sinT[SEQ * 64];

// ---------------- PTX helpers ----------------------------------------------
__device__ __forceinline__ uint32_t smem_u32(const void* p) {
    uint32_t a;
    asm("{ .reg .u64 t; cvta.to.shared.u64 t, %1; cvt.u32.u64 %0, t; }" : "=r"(a) : "l"(p));
    return a;
}

#define CP_ASYNC16(dst, src) \
    asm volatile("cp.async.cg.shared.global [%0], [%1], 16;" :: "r"(dst), "l"(src) : "memory")
#define CP_COMMIT() asm volatile("cp.async.commit_group;" ::: "memory")
#define CP_WAIT(n)  asm volatile("cp.async.wait_group %0;" :: "n"(n) : "memory")

#define LDSM_X4(r0, r1, r2, r3, addr) \
    asm volatile("ldmatrix.sync.aligned.m8n8.x4.shared.b16 {%0,%1,%2,%3}, [%4];" \
        : "=r"(r0), "=r"(r1), "=r"(r2), "=r"(r3) : "r"(addr))

#define MMA_BF16(d, a, b) \
    asm volatile("mma.sync.aligned.m16n8k16.row.col.f32.bf16.bf16.f32 " \
        "{%0,%1,%2,%3}, {%4,%5,%6,%7}, {%8,%9}, {%0,%1,%2,%3};" \
        : "+f"((d)[0]), "+f"((d)[1]), "+f"((d)[2]), "+f"((d)[3]) \
        : "r"((a)[0]), "r"((a)[1]), "r"((a)[2]), "r"((a)[3]), \
          "r"((b)[0]), "r"((b)[1]))

// ---------------- conversion kernels ---------------------------------------
__global__ __launch_bounds__(256) void split_kernel(
    const float* __restrict__ X, __nv_bfloat16* __restrict__ H,
    __nv_bfloat16* __restrict__ L)
{
    size_t i = (size_t)blockIdx.x * 256 + threadIdx.x;   // one float4 per thread
    float4 v = reinterpret_cast<const float4*>(X)[i];
    float a[4] = {v.x, v.y, v.z, v.w};
    __nv_bfloat162* H2 = reinterpret_cast<__nv_bfloat162*>(H);
    __nv_bfloat162* L2 = reinterpret_cast<__nv_bfloat162*>(L);
#pragma unroll
    for (int p = 0; p < 2; p++) {
        __nv_bfloat16 h0 = __float2bfloat16(a[p*2+0]);
        __nv_bfloat16 h1 = __float2bfloat16(a[p*2+1]);
        __nv_bfloat16 l0 = __float2bfloat16(a[p*2+0] - __bfloat162float(h0));
        __nv_bfloat16 l1 = __float2bfloat16(a[p*2+1] - __bfloat162float(h1));
        H2[i*2 + p] = __nv_bfloat162{h0, h1};
        L2[i*2 + p] = __nv_bfloat162{l0, l1};
    }
}

// W [K,N] f32 -> Th/Tl [N,K] bf16 (transpose + split)
__global__ __launch_bounds__(256) void transpose_split_kernel(
    const float* __restrict__ W, __nv_bfloat16* __restrict__ Th,
    __nv_bfloat16* __restrict__ Tl, int K, int N)
{
    __shared__ float tile[32][33];
    int n0 = blockIdx.x * 32, k0 = blockIdx.y * 32;
    int tx = threadIdx.x & 31, ty = threadIdx.x >> 5;   // 32 x 8
#pragma unroll
    for (int j = 0; j < 32; j += 8)
        tile[ty + j][tx] = W[(size_t)(k0 + ty + j) * N + n0 + tx];
    __syncthreads();
#pragma unroll
    for (int j = 0; j < 32; j += 8) {
        float v = tile[tx][ty + j];
        __nv_bfloat16 h = __float2bfloat16(v);
        __nv_bfloat16 l = __float2bfloat16(v - __bfloat162float(h));
        size_t o = (size_t)(n0 + ty + j) * K + k0 + tx;
        Th[o] = h; Tl[o] = l;
    }
}

// ---------------- RoPE table + apply ---------------------------------------
__global__ __launch_bounds__(256) void rope_table_kernel(
    float* __restrict__ cosT, float* __restrict__ sinT)
{
    int idx = blockIdx.x * 256 + threadIdx.x;   // SEQ*64
    int d2 = idx & 63, s = idx >> 6;
    float invf = expf(-(float)d2 * (9.210340371976184f / 64.0f));
    float ang  = (float)s * invf;
    double sv, cv;
    sincos((double)ang, &sv, &cv);
    cosT[idx] = (float)cv;
    sinT[idx] = (float)sv;
}

__global__ __launch_bounds__(256) void rope_kernel(
    const float* __restrict__ raw, float* __restrict__ out, int nheads,
    const float* __restrict__ cosT, const float* __restrict__ sinT)
{
    int idx = blockIdx.x * 256 + threadIdx.x;       // B*nheads*S*64 threads
    int d2 = idx & 63;
    int t  = idx >> 6;
    int s  = t & (SEQ - 1);
    t >>= 11;
    int h = t % nheads;
    int b = t / nheads;
    if (b >= BATCH) return;

    const float* row = raw + ((size_t)(b * SEQ + s)) * (nheads * HDIM) + h * HDIM;
    float x0 = row[d2], x1 = row[d2 + 64];
    float c  = cosT[s * 64 + d2];
    float sn = sinT[s * 64 + d2];
    float o0 = x0 * c - x1 * sn;
    float o1 = x1 * c + x0 * sn;
    float* orow = out + ((size_t)((b * nheads + h) * SEQ + s)) * HDIM;
    orow[d2]      = o0;
    orow[d2 + 64] = o1;
}

// ---------------- mma.sync split-bf16 GEMM ---------------------------------
// C[M,N] = A[M,4096] @ Bt[N,4096]^T.  A, Bt as hi/lo bf16 pairs.
// CTA 128x128, BK=32, 256 thr = 8 warps (4 M x 2 N), warp tile 32x64.
// Smem per stage (32 KB): Ahi[8K] Alo[8K] Bhi[8K] Blo[8K].
// Tile layout: row r (0..127) holds 32 bf16 (64B) as four 16B chunks at
//   off = r*64 + ((chunk ^ ((r>>1)&3)) << 4)   -- conflict-free for both
//   cp.async writes and ldmatrix reads (banks 16*(r&1) + 4*(c^((r>>1)&3))).
#define GEMM_SMEM (2 * 32768)

__device__ __forceinline__ void load_stage(
    uint32_t sb, int tid,
    const __nv_bfloat16* __restrict__ Ahi, const __nv_bfloat16* __restrict__ Alo,
    const __nv_bfloat16* __restrict__ Bhi, const __nv_bfloat16* __restrict__ Blo,
    int m0, int n0, int k0)
{
#pragma unroll
    for (int it = 0; it < 8; it++) {
        int id = tid + it * 256;
        int mat = id >> 9;                 // 0..3
        int w = id & 511;
        int r = w >> 2, c = w & 3;
        uint32_t so = sb + mat * 8192 + r * 64 + (((c ^ ((r >> 1) & 3))) << 4);
        const __nv_bfloat16* src;
        if      (mat == 0) src = Ahi + (size_t)(m0 + r) * 4096 + k0 + c * 8;
        else if (mat == 1) src = Alo + (size_t)(m0 + r) * 4096 + k0 + c * 8;
        else if (mat == 2) src = Bhi + (size_t)(n0 + r) * 4096 + k0 + c * 8;
        else               src = Blo + (size_t)(n0 + r) * 4096 + k0 + c * 8;
        CP_ASYNC16(so, src);
    }
}

__global__ __launch_bounds__(256) void gemm_mma_kernel(
    const __nv_bfloat16* __restrict__ Ahi, const __nv_bfloat16* __restrict__ Alo,
    const __nv_bfloat16* __restrict__ Bhi, const __nv_bfloat16* __restrict__ Blo,
    float* __restrict__ C, int N)
{
    extern __shared__ __align__(1024) char smem[];
    uint32_t sb = smem_u32(smem);
    const int tid = threadIdx.x;
    const int lane = tid & 31, wid = tid >> 5;
    const int warp_m = wid & 3, warp_n = wid >> 2;      // 4 x 2
    const int m0 = blockIdx.y * 128, n0 = blockIdx.x * 128;

    float acc[2][8][4];
#pragma unroll
    for (int mt = 0; mt < 2; mt++)
#pragma unroll
        for (int nt = 0; nt < 8; nt++)
#pragma unroll
            for (int q = 0; q < 4; q++) acc[mt][nt][q] = 0.f;

    load_stage(sb, tid, Ahi, Alo, Bhi, Blo, m0, n0, 0);
    CP_COMMIT();

    const uint32_t aRowB = warp_m * 32 + (lane & 15);         // + mt*16
    const int aKh = lane >> 4;                                // 0/1
    const uint32_t bRowB = warp_n * 64 + (lane & 7) + ((lane >> 4) & 1) * 8; // + p*16
    const int bKh = (lane >> 3) & 1;                          // 0/1

    for (int kb = 0; kb < 128; kb++) {
        const uint32_t s_off = (uint32_t)(kb & 1) * 32768;
        if (kb + 1 < 128) {
            load_stage(sb + ((kb + 1) & 1) * 32768, tid, Ahi, Alo, Bhi, Blo,
                       m0, n0, (kb + 1) * 32);
            CP_COMMIT();
            CP_WAIT(1);
        } else {
            CP_WAIT(0);
        }
        __syncthreads();

#pragma unroll
        for (int kk = 0; kk < 2; kk++) {          // k offsets 0, 16
            uint32_t ah[2][4], al[2][4];
#pragma unroll
            for (int mt = 0; mt < 2; mt++) {
                uint32_t r = aRowB + mt * 16;
                uint32_t chunk = (uint32_t)(kk * 2 + aKh);
                uint32_t off = r * 64 + ((chunk ^ ((r >> 1) & 3)) << 4);
                LDSM_X4(ah[mt][0], ah[mt][1], ah[mt][2], ah[mt][3], sb + s_off + off);
                LDSM_X4(al[mt][0], al[mt][1], al[mt][2], al[mt][3], sb + s_off + 8192 + off);
            }
#pragma unroll
            for (int p = 0; p < 4; p++) {
                uint32_t r = bRowB + p * 16;
                uint32_t chunk = (uint32_t)(kk * 2 + bKh);
                uint32_t off = r * 64 + ((chunk ^ ((r >> 1) & 3)) << 4);
                uint32_t bh[4], bl[4];
                LDSM_X4(bh[0], bh[1], bh[2], bh[3], sb + s_off + 16384 + off);
                LDSM_X4(bl[0], bl[1], bl[2], bl[3], sb + s_off + 24576 + off);
#pragma unroll
                for (int mt = 0; mt < 2; mt++) {
                    MMA_BF16(acc[mt][2*p],     ah[mt], bh + 0);
                    MMA_BF16(acc[mt][2*p],     ah[mt], bl + 0);
                    MMA_BF16(acc[mt][2*p],     al[mt], bh + 0);
                    MMA_BF16(acc[mt][2*p + 1], ah[mt], bh + 2);
                    MMA_BF16(acc[mt][2*p + 1], ah[mt], bl + 2);
                    MMA_BF16(acc[mt][2*p + 1], al[mt], bh + 2);
                }
            }
        }
        __syncthreads();
    }

    // epilogue
#pragma unroll
    for (int mt = 0; mt < 2; mt++) {
        int row = m0 + warp_m * 32 + mt * 16 + (lane >> 2);
#pragma unroll
        for (int nt = 0; nt < 8; nt++) {
            int col = n0 + warp_n * 64 + nt * 8 + (lane & 3) * 2;
            *reinterpret_cast<float2*>(C + (size_t)row * N + col) =
                float2{acc[mt][nt][0], acc[mt][nt][1]};
            *reinterpret_cast<float2*>(C + (size_t)(row + 8) * N + col) =
                float2{acc[mt][nt][2], acc[mt][nt][3]};
        }
    }
}

// ---------------- Flash attention (fp32, causal, online softmax) -----------
#define FLASH_SMEM_FLOATS (3 * 64 * 129 + 64 * 65)
__global__ __launch_bounds__(256) void flash_kernel(
    const float* __restrict__ Q, const float* __restrict__ K,
    const float* __restrict__ Vraw, float* __restrict__ O)
{
    extern __shared__ float sm[];
    float* Qs = sm;                 // [64][129]
    float* Ks = Qs + 64 * 129;
    float* Vs = Ks + 64 * 129;
    float* Ps = Vs + 64 * 129;      // [64][65]

    const int tid = threadIdx.x;
    const int tx = tid & 15, ty = tid >> 4;
    const int m0 = blockIdx.x * 64;
    const int bh = blockIdx.y;
    const int b = bh >> 5, h = bh & 31;
    const int kv = h >> 2;
    const float scale = 0.08838834764831845f;

    const float* Qbase = Q + ((size_t)(b * NHEADS + h) * SEQ + m0) * HDIM;
    const float* Kbase = K + (size_t)(b * NKV + kv) * SEQ * HDIM;
    const float* Vbase = Vraw + (size_t)b * SEQ * KVW + kv * HDIM;

    for (int i = tid; i < 64 * 32; i += 256) {
        int r = i >> 5, c4 = (i & 31) << 2;
        float4 v = *reinterpret_cast<const float4*>(Qbase + (size_t)r * HDIM + c4);
        float* d = &Qs[r * 129 + c4];
        d[0] = v.x; d[1] = v.y; d[2] = v.z; d[3] = v.w;
    }

    float acc[4][8];
#pragma unroll
    for (int r = 0; r < 4; r++)
#pragma unroll
        for (int c = 0; c < 8; c++) acc[r][c] = 0.f;
    float mi[4] = {-INFINITY, -INFINITY, -INFINITY, -INFINITY};
    float li[4] = {0.f, 0.f, 0.f, 0.f};

    const int nb = blockIdx.x + 1;
    for (int kb = 0; kb < nb; kb++) {
        const int n0 = kb * 64;
        __syncthreads();
        for (int i = tid; i < 64 * 32; i += 256) {
            int r = i >> 5, c4 = (i & 31) << 2;
            float4 v = *reinterpret_cast<const float4*>(Kbase + (size_t)(n0 + r) * HDIM + c4);
            float* d = &Ks[r * 129 + c4];
            d[0] = v.x; d[1] = v.y; d[2] = v.z; d[3] = v.w;
            float4 w = *reinterpret_cast<const float4*>(Vbase + (size_t)(n0 + r) * KVW + c4);
            float* e = &Vs[r * 129 + c4];
            e[0] = w.x; e[1] = w.y; e[2] = w.z; e[3] = w.w;
        }
        __syncthreads();

        float s[4][4];
#pragma unroll
        for (int r = 0; r < 4; r++)
#pragma unroll
            for (int c = 0; c < 4; c++) s[r][c] = 0.f;
#pragma unroll 4
        for (int d = 0; d < 128; d++) {
            float qa[4], ka[4];
#pragma unroll
            for (int r = 0; r < 4; r++) qa[r] = Qs[(ty * 4 + r) * 129 + d];
#pragma unroll
            for (int c = 0; c < 4; c++) ka[c] = Ks[(tx + 16 * c) * 129 + d];
#pragma unroll
            for (int r = 0; r < 4; r++)
#pragma unroll
                for (int c = 0; c < 4; c++) s[r][c] += qa[r] * ka[c];
        }

#pragma unroll
        for (int r = 0; r < 4; r++) {
            const int qi = m0 + ty * 4 + r;
            float mx = -INFINITY;
#pragma unroll
            for (int c = 0; c < 4; c++) {
                int kj = n0 + tx + 16 * c;
                s[r][c] = (kj <= qi) ? s[r][c] * scale : -INFINITY;
                mx = fmaxf(mx, s[r][c]);
            }
#pragma unroll
            for (int o = 8; o; o >>= 1) mx = fmaxf(mx, __shfl_xor_sync(0xffffffffu, mx, o));
            float mtot  = fmaxf(mi[r], mx);
            float alpha = __expf(mi[r] - mtot);
            mi[r] = mtot;
            float lsum = 0.f;
#pragma unroll
            for (int c = 0; c < 4; c++) {
                float p = __expf(s[r][c] - mtot);
                s[r][c] = p;
                lsum += p;
            }
#pragma unroll
            for (int o = 8; o; o >>= 1) lsum += __shfl_xor_sync(0xffffffffu, lsum, o);
            li[r] = li[r] * alpha + lsum;
#pragma unroll
            for (int c = 0; c < 8; c++) acc[r][c] *= alpha;
#pragma unroll
            for (int c = 0; c < 4; c++) Ps[(ty * 4 + r) * 65 + tx + 16 * c] = s[r][c];
        }
        __syncwarp();

#pragma unroll 2
        for (int kj = 0; kj < 64; kj++) {
            float pv[4], vv[8];
#pragma unroll
            for (int r = 0; r < 4; r++) pv[r] = Ps[(ty * 4 + r) * 65 + kj];
#pragma unroll
            for (int c = 0; c < 8; c++) vv[c] = Vs[kj * 129 + tx + 16 * c];
#pragma unroll
            for (int r = 0; r < 4; r++)
#pragma unroll
                for (int c = 0; c < 8; c++) acc[r][c] += pv[r] * vv[c];
        }
    }

#pragma unroll
    for (int r = 0; r < 4; r++) {
        float inv = 1.f / li[r];
        int qi = m0 + ty * 4 + r;
        float* orow = O + ((size_t)(b * SEQ + qi)) * DMODEL + h * HDIM;
#pragma unroll
        for (int c = 0; c < 8; c++) orow[tx + 16 * c] = acc[r][c] * inv;
    }
}

// ---------------- launch ----------------------------------------------------
extern "C" void kernel_launch(void* const* d_in, const int* in_sizes, int n_in,
                              void* d_out, int out_size)
{
    (void)in_sizes; (void)n_in; (void)out_size;
    const float* x  = (const float*)d_in[0];
    const float* Wq = (const float*)d_in[2];
    const float* Wk = (const float*)d_in[3];
    const float* Wv = (const float*)d_in[4];
    const float* Wo = (const float*)d_in[5];
    float* out = (float*)d_out;

    float *rawQ, *rawK, *rawV, *Qr, *Kr, *Ob, *cosT, *sinT;
    __nv_bfloat16 *xhi, *xlo, *Ohi, *Olo;
    __nv_bfloat16 *Wqh, *Wql, *Wkh, *Wkl, *Wvh, *Wvl, *Woh, *Wol;
    cudaGetSymbolAddress((void**)&rawQ, g_rawQ);
    cudaGetSymbolAddress((void**)&rawK, g_rawK);
    cudaGetSymbolAddress((void**)&rawV, g_rawV);
    cudaGetSymbolAddress((void**)&Qr,   g_Q);
    cudaGetSymbolAddress((void**)&Kr,   g_K);
    cudaGetSymbolAddress((void**)&Ob,   g_O);
    cudaGetSymbolAddress((void**)&cosT, g_cosT);
    cudaGetSymbolAddress((void**)&sinT, g_sinT);
    cudaGetSymbolAddress((void**)&xhi,  g_xhi);
    cudaGetSymbolAddress((void**)&xlo,  g_xlo);
    cudaGetSymbolAddress((void**)&Ohi,  g_Ohi);
    cudaGetSymbolAddress((void**)&Olo,  g_Olo);
    cudaGetSymbolAddress((void**)&Wqh,  g_Wqt_h);
    cudaGetSymbolAddress((void**)&Wql,  g_Wqt_l);
    cudaGetSymbolAddress((void**)&Wkh,  g_Wkt_h);
    cudaGetSymbolAddress((void**)&Wkl,  g_Wkt_l);
    cudaGetSymbolAddress((void**)&Wvh,  g_Wvt_h);
    cudaGetSymbolAddress((void**)&Wvl,  g_Wvt_l);
    cudaGetSymbolAddress((void**)&Woh,  g_Wot_h);
    cudaGetSymbolAddress((void**)&Wol,  g_Wot_l);

    const int flash_smem = FLASH_SMEM_FLOATS * (int)sizeof(float);
    cudaFuncSetAttribute(flash_kernel, cudaFuncAttributeMaxDynamicSharedMemorySize, flash_smem);
    cudaFuncSetAttribute(gemm_mma_kernel, cudaFuncAttributeMaxDynamicSharedMemorySize, GEMM_SMEM);

    // operand prep
    split_kernel<<<((size_t)MROWS * DMODEL / 4) / 256, 256>>>(x, xhi, xlo);
    transpose_split_kernel<<<dim3(DMODEL/32, DMODEL/32), 256>>>(Wq, Wqh, Wql, DMODEL, DMODEL);
    transpose_split_kernel<<<dim3(KVW/32,    DMODEL/32), 256>>>(Wk, Wkh, Wkl, DMODEL, KVW);
    transpose_split_kernel<<<dim3(KVW/32,    DMODEL/32), 256>>>(Wv, Wvh, Wvl, DMODEL, KVW);
    transpose_split_kernel<<<dim3(DMODEL/32, DMODEL/32), 256>>>(Wo, Woh, Wol, DMODEL, DMODEL);
    rope_table_kernel<<<(SEQ * 64) / 256, 256>>>(cosT, sinT);

    // QKV projections (mma.sync split-bf16)
    gemm_mma_kernel<<<dim3(DMODEL/128, MROWS/128), 256, GEMM_SMEM>>>(xhi, xlo, Wqh, Wql, rawQ, DMODEL);
    gemm_mma_kernel<<<dim3(KVW/128,    MROWS/128), 256, GEMM_SMEM>>>(xhi, xlo, Wkh, Wkl, rawK, KVW);
    gemm_mma_kernel<<<dim3(KVW/128,    MROWS/128), 256, GEMM_SMEM>>>(xhi, xlo, Wvh, Wvl, rawV, KVW);

    // RoPE + relayout
    rope_kernel<<<(BATCH * NHEADS * SEQ * 64) / 256, 256>>>(rawQ, Qr, NHEADS, cosT, sinT);
    rope_kernel<<<(BATCH * NKV    * SEQ * 64) / 256, 256>>>(rawK, Kr, NKV, cosT, sinT);

    // causal flash attention (fp32)
    flash_kernel<<<dim3(SEQ / 64, BATCH * NHEADS), 256, flash_smem>>>(Qr, Kr, rawV, Ob);

    // output projection
    split_kernel<<<((size_t)MROWS * DMODEL / 4) / 256, 256>>>(Ob, Ohi, Olo);
    gemm_mma_kernel<<<dim3(DMODEL/128, MROWS/128), 256, GEMM_SMEM>>>(Ohi, Olo, Woh, Wol, out, DMODEL);
}

// round 7
// speedup vs baseline: 4.8167x; 1.4362x over previous
#include <cuda_runtime.h>
#include <cuda_bf16.h>
#include <math.h>
#include <stdint.h>

#define BATCH  2
#define SEQ    2048
#define DMODEL 4096
#define NHEADS 32
#define NKV    8
#define HDIM   128
#define MROWS  (BATCH*SEQ)        // 4096
#define KVW    (NKV*HDIM)         // 1024

// ---------------- scratch (static device buffers; no cudaMalloc) -----------
__device__ __align__(256) float g_rawQ[(size_t)MROWS * DMODEL];
__device__ __align__(256) float g_rawK[(size_t)MROWS * KVW];
__device__ __align__(256) float g_rawV[(size_t)MROWS * KVW];

// split-bf16 operands
__device__ __align__(256) __nv_bfloat16 g_xhi[(size_t)MROWS * DMODEL];
__device__ __align__(256) __nv_bfloat16 g_xlo[(size_t)MROWS * DMODEL];
__device__ __align__(256) __nv_bfloat16 g_Ohi[(size_t)MROWS * DMODEL];
__device__ __align__(256) __nv_bfloat16 g_Olo[(size_t)MROWS * DMODEL];
// roped Q/K bf16 hi/lo, head-major
__device__ __align__(256) __nv_bfloat16 g_Qhi[(size_t)MROWS * DMODEL];
__device__ __align__(256) __nv_bfloat16 g_Qlo[(size_t)MROWS * DMODEL];
__device__ __align__(256) __nv_bfloat16 g_Khi[(size_t)MROWS * KVW];
__device__ __align__(256) __nv_bfloat16 g_Klo[(size_t)MROWS * KVW];
// V transposed [B,KV,HDIM,SEQ] bf16 hi/lo
__device__ __align__(256) __nv_bfloat16 g_Vth[(size_t)MROWS * KVW];
__device__ __align__(256) __nv_bfloat16 g_Vtl[(size_t)MROWS * KVW];
// transposed weights [N, K] bf16 hi/lo
__device__ __align__(256) __nv_bfloat16 g_Wqt_h[(size_t)DMODEL * DMODEL];
__device__ __align__(256) __nv_bfloat16 g_Wqt_l[(size_t)DMODEL * DMODEL];
__device__ __align__(256) __nv_bfloat16 g_Wkt_h[(size_t)KVW * DMODEL];
__device__ __align__(256) __nv_bfloat16 g_Wkt_l[(size_t)KVW * DMODEL];
__device__ __align__(256) __nv_bfloat16 g_Wvt_h[(size_t)KVW * DMODEL];
__device__ __align__(256) __nv_bfloat16 g_Wvt_l[(size_t)KVW * DMODEL];
__device__ __align__(256) __nv_bfloat16 g_Wot_h[(size_t)DMODEL * DMODEL];
__device__ __align__(256) __nv_bfloat16 g_Wot_l[(size_t)DMODEL * DMODEL];
// RoPE tables
__device__ __align__(256) float g_cosT[SEQ * 64];
__device__ __align__(256) float g_sinT[SEQ * 64];

// ---------------- PTX helpers ----------------------------------------------
__device__ __forceinline__ uint32_t smem_u32(const void* p) {
    uint32_t a;
    asm("{ .reg .u64 t; cvta.to.shared.u64 t, %1; cvt.u32.u64 %0, t; }" : "=r"(a) : "l"(p));
    return a;
}

#define CP_ASYNC16(dst, src) \
    asm volatile("cp.async.cg.shared.global [%0], [%1], 16;" :: "r"(dst), "l"(src) : "memory")
#define CP_COMMIT() asm volatile("cp.async.commit_group;" ::: "memory")
#define CP_WAIT(n)  asm volatile("cp.async.wait_group %0;" :: "n"(n) : "memory")

#define LDSM_X4(r0, r1, r2, r3, addr) \
    asm volatile("ldmatrix.sync.aligned.m8n8.x4.shared.b16 {%0,%1,%2,%3}, [%4];" \
        : "=r"(r0), "=r"(r1), "=r"(r2), "=r"(r3) : "r"(addr))

#define MMA_BF16(d, a, b) \
    asm volatile("mma.sync.aligned.m16n8k16.row.col.f32.bf16.bf16.f32 " \
        "{%0,%1,%2,%3}, {%4,%5,%6,%7}, {%8,%9}, {%0,%1,%2,%3};" \
        : "+f"((d)[0]), "+f"((d)[1]), "+f"((d)[2]), "+f"((d)[3]) \
        : "r"((a)[0]), "r"((a)[1]), "r"((a)[2]), "r"((a)[3]), \
          "r"((b)[0]), "r"((b)[1]))

// chunk-tile addressing: tile = [rows][32 bf16 cols], row r = 64B of four 16B
// groups, group g at ((g ^ ((r>>1)&3)) << 4).  Validated in R4 GEMM.
#define TOFF(r, g) ((uint32_t)((r) * 64 + ((((g) ^ (((r) >> 1) & 3))) << 4)))

// ---------------- conversion kernels ---------------------------------------
__global__ __launch_bounds__(256) void split_kernel(
    const float* __restrict__ X, __nv_bfloat16* __restrict__ H,
    __nv_bfloat16* __restrict__ L)
{
    size_t i = (size_t)blockIdx.x * 256 + threadIdx.x;
    float4 v = reinterpret_cast<const float4*>(X)[i];
    float a[4] = {v.x, v.y, v.z, v.w};
    __nv_bfloat162* H2 = reinterpret_cast<__nv_bfloat162*>(H);
    __nv_bfloat162* L2 = reinterpret_cast<__nv_bfloat162*>(L);
#pragma unroll
    for (int p = 0; p < 2; p++) {
        __nv_bfloat16 h0 = __float2bfloat16(a[p*2+0]);
        __nv_bfloat16 h1 = __float2bfloat16(a[p*2+1]);
        __nv_bfloat16 l0 = __float2bfloat16(a[p*2+0] - __bfloat162float(h0));
        __nv_bfloat16 l1 = __float2bfloat16(a[p*2+1] - __bfloat162float(h1));
        H2[i*2 + p] = __nv_bfloat162{h0, h1};
        L2[i*2 + p] = __nv_bfloat162{l0, l1};
    }
}

__global__ __launch_bounds__(256) void transpose_split_kernel(
    const float* __restrict__ W, __nv_bfloat16* __restrict__ Th,
    __nv_bfloat16* __restrict__ Tl, int K, int N)
{
    __shared__ float tile[32][33];
    int n0 = blockIdx.x * 32, k0 = blockIdx.y * 32;
    int tx = threadIdx.x & 31, ty = threadIdx.x >> 5;
#pragma unroll
    for (int j = 0; j < 32; j += 8)
        tile[ty + j][tx] = W[(size_t)(k0 + ty + j) * N + n0 + tx];
    __syncthreads();
#pragma unroll
    for (int j = 0; j < 32; j += 8) {
        float v = tile[tx][ty + j];
        __nv_bfloat16 h = __float2bfloat16(v);
        __nv_bfloat16 l = __float2bfloat16(v - __bfloat162float(h));
        size_t o = (size_t)(n0 + ty + j) * K + k0 + tx;
        Th[o] = h; Tl[o] = l;
    }
}

// rawV [B,S,KVW] f32 -> Vt hi/lo [B*KV, HDIM, SEQ] bf16
__global__ __launch_bounds__(256) void vtrans_split_kernel(
    const float* __restrict__ V, __nv_bfloat16* __restrict__ Th,
    __nv_bfloat16* __restrict__ Tl)
{
    __shared__ float tile[32][33];
    int s0 = blockIdx.x * 32, d0 = blockIdx.y * 32, bkv = blockIdx.z;
    int b = bkv >> 3, kvh = bkv & 7;
    int tx = threadIdx.x & 31, ty = threadIdx.x >> 5;
#pragma unroll
    for (int j = 0; j < 32; j += 8)
        tile[ty + j][tx] = V[((size_t)(b * SEQ) + s0 + ty + j) * KVW + kvh * HDIM + d0 + tx];
    __syncthreads();
#pragma unroll
    for (int j = 0; j < 32; j += 8) {
        float v = tile[tx][ty + j];
        __nv_bfloat16 h = __float2bfloat16(v);
        __nv_bfloat16 l = __float2bfloat16(v - __bfloat162float(h));
        size_t o = ((size_t)bkv * HDIM + d0 + ty + j) * SEQ + s0 + tx;
        Th[o] = h; Tl[o] = l;
    }
}

// ---------------- RoPE table + apply (outputs bf16 hi/lo) ------------------
__global__ __launch_bounds__(256) void rope_table_kernel(
    float* __restrict__ cosT, float* __restrict__ sinT)
{
    int idx = blockIdx.x * 256 + threadIdx.x;
    int d2 = idx & 63, s = idx >> 6;
    float invf = expf(-(float)d2 * (9.210340371976184f / 64.0f));
    float ang  = (float)s * invf;
    double sv, cv;
    sincos((double)ang, &sv, &cv);
    cosT[idx] = (float)cv;
    sinT[idx] = (float)sv;
}

__global__ __launch_bounds__(256) void rope_split_kernel(
    const float* __restrict__ raw, __nv_bfloat16* __restrict__ Oh,
    __nv_bfloat16* __restrict__ Ol, int nheads,
    const float* __restrict__ cosT, const float* __restrict__ sinT)
{
    int idx = blockIdx.x * 256 + threadIdx.x;
    int d2 = idx & 63;
    int t  = idx >> 6;
    int s  = t & (SEQ - 1);
    t >>= 11;
    int h = t % nheads;
    int b = t / nheads;
    if (b >= BATCH) return;

    const float* row = raw + ((size_t)(b * SEQ + s)) * (nheads * HDIM) + h * HDIM;
    float x0 = row[d2], x1 = row[d2 + 64];
    float c  = cosT[s * 64 + d2];
    float sn = sinT[s * 64 + d2];
    float o0 = x0 * c - x1 * sn;
    float o1 = x1 * c + x0 * sn;
    size_t ob = ((size_t)((b * nheads + h) * SEQ + s)) * HDIM;
    __nv_bfloat16 h0 = __float2bfloat16(o0);
    __nv_bfloat16 h1 = __float2bfloat16(o1);
    Oh[ob + d2]      = h0;
    Oh[ob + d2 + 64] = h1;
    Ol[ob + d2]      = __float2bfloat16(o0 - __bfloat162float(h0));
    Ol[ob + d2 + 64] = __float2bfloat16(o1 - __bfloat162float(h1));
}

// ---------------- mma.sync split-bf16 GEMM (unchanged, validated R4) -------
#define GEMM_SMEM (2 * 32768)

__device__ __forceinline__ void load_stage(
    uint32_t sb, int tid,
    const __nv_bfloat16* __restrict__ Ahi, const __nv_bfloat16* __restrict__ Alo,
    const __nv_bfloat16* __restrict__ Bhi, const __nv_bfloat16* __restrict__ Blo,
    int m0, int n0, int k0)
{
#pragma unroll
    for (int it = 0; it < 8; it++) {
        int id = tid + it * 256;
        int mat = id >> 9;
        int w = id & 511;
        int r = w >> 2, c = w & 3;
        uint32_t so = sb + mat * 8192 + r * 64 + (((c ^ ((r >> 1) & 3))) << 4);
        const __nv_bfloat16* src;
        if      (mat == 0) src = Ahi + (size_t)(m0 + r) * 4096 + k0 + c * 8;
        else if (mat == 1) src = Alo + (size_t)(m0 + r) * 4096 + k0 + c * 8;
        else if (mat == 2) src = Bhi + (size_t)(n0 + r) * 4096 + k0 + c * 8;
        else               src = Blo + (size_t)(n0 + r) * 4096 + k0 + c * 8;
        CP_ASYNC16(so, src);
    }
}

__global__ __launch_bounds__(256) void gemm_mma_kernel(
    const __nv_bfloat16* __restrict__ Ahi, const __nv_bfloat16* __restrict__ Alo,
    const __nv_bfloat16* __restrict__ Bhi, const __nv_bfloat16* __restrict__ Blo,
    float* __restrict__ C, int N)
{
    extern __shared__ __align__(1024) char smem[];
    uint32_t sb = smem_u32(smem);
    const int tid = threadIdx.x;
    const int lane = tid & 31, wid = tid >> 5;
    const int warp_m = wid & 3, warp_n = wid >> 2;
    const int m0 = blockIdx.y * 128, n0 = blockIdx.x * 128;

    float acc[2][8][4];
#pragma unroll
    for (int mt = 0; mt < 2; mt++)
#pragma unroll
        for (int nt = 0; nt < 8; nt++)
#pragma unroll
            for (int q = 0; q < 4; q++) acc[mt][nt][q] = 0.f;

    load_stage(sb, tid, Ahi, Alo, Bhi, Blo, m0, n0, 0);
    CP_COMMIT();

    const uint32_t aRowB = warp_m * 32 + (lane & 15);
    const int aKh = lane >> 4;
    const uint32_t bRowB = warp_n * 64 + (lane & 7) + ((lane >> 4) & 1) * 8;
    const int bKh = (lane >> 3) & 1;

    for (int kb = 0; kb < 128; kb++) {
        const uint32_t s_off = (uint32_t)(kb & 1) * 32768;
        if (kb + 1 < 128) {
            load_stage(sb + ((kb + 1) & 1) * 32768, tid, Ahi, Alo, Bhi, Blo,
                       m0, n0, (kb + 1) * 32);
            CP_COMMIT();
            CP_WAIT(1);
        } else {
            CP_WAIT(0);
        }
        __syncthreads();

#pragma unroll
        for (int kk = 0; kk < 2; kk++) {
            uint32_t ah[2][4], al[2][4];
#pragma unroll
            for (int mt = 0; mt < 2; mt++) {
                uint32_t r = aRowB + mt * 16;
                uint32_t chunk = (uint32_t)(kk * 2 + aKh);
                uint32_t off = r * 64 + ((chunk ^ ((r >> 1) & 3)) << 4);
                LDSM_X4(ah[mt][0], ah[mt][1], ah[mt][2], ah[mt][3], sb + s_off + off);
                LDSM_X4(al[mt][0], al[mt][1], al[mt][2], al[mt][3], sb + s_off + 8192 + off);
            }
#pragma unroll
            for (int p = 0; p < 4; p++) {
                uint32_t r = bRowB + p * 16;
                uint32_t chunk = (uint32_t)(kk * 2 + bKh);
                uint32_t off = r * 64 + ((chunk ^ ((r >> 1) & 3)) << 4);
                uint32_t bh[4], bl[4];
                LDSM_X4(bh[0], bh[1], bh[2], bh[3], sb + s_off + 16384 + off);
                LDSM_X4(bl[0], bl[1], bl[2], bl[3], sb + s_off + 24576 + off);
#pragma unroll
                for (int mt = 0; mt < 2; mt++) {
                    MMA_BF16(acc[mt][2*p],     ah[mt], bh + 0);
                    MMA_BF16(acc[mt][2*p],     ah[mt], bl + 0);
                    MMA_BF16(acc[mt][2*p],     al[mt], bh + 0);
                    MMA_BF16(acc[mt][2*p + 1], ah[mt], bh + 2);
                    MMA_BF16(acc[mt][2*p + 1], ah[mt], bl + 2);
                    MMA_BF16(acc[mt][2*p + 1], al[mt], bh + 2);
                }
            }
        }
        __syncthreads();
    }

#pragma unroll
    for (int mt = 0; mt < 2; mt++) {
        int row = m0 + warp_m * 32 + mt * 16 + (lane >> 2);
#pragma unroll
        for (int nt = 0; nt < 8; nt++) {
            int col = n0 + warp_n * 64 + nt * 8 + (lane & 3) * 2;
            *reinterpret_cast<float2*>(C + (size_t)row * N + col) =
                float2{acc[mt][nt][0], acc[mt][nt][1]};
            *reinterpret_cast<float2*>(C + (size_t)(row + 8) * N + col) =
                float2{acc[mt][nt][2], acc[mt][nt][3]};
        }
    }
}

// ---------------- flash attention on mma.sync (split-bf16) -----------------
// q tile 64 x kv tile 64, 8 warps (warp_m 2 x warp_n 4).
// smem: Q hi/lo resident; K,Vt hi/lo double-buffered; P hi/lo; row stats.
#define F_QHI  0
#define F_QLO  16384
#define F_STG  32768            /* + stage*65536 */
#define F_KHI  0
#define F_KLO  16384
#define F_VHI  32768
#define F_VLO  49152
#define F_PHI  163840
#define F_PLO  172032
#define F_STAT 180224
#define F_SMEM 183296

__device__ __forceinline__ void flash_load_stage(
    uint32_t st, int tid,
    const __nv_bfloat16* __restrict__ Kh, const __nv_bfloat16* __restrict__ Kl,
    const __nv_bfloat16* __restrict__ Vh, const __nv_bfloat16* __restrict__ Vl,
    int n0)
{
#pragma unroll
    for (int it = 0; it < 4; it++) {            // K hi/lo: 64 rows x 128 cols
        int id = tid + it * 256;                // 0..1023
        int r = id >> 4, cg = id & 15, c = cg >> 2, g = cg & 3;
        uint32_t off = (uint32_t)(c * 4096) + TOFF(r, g);
        CP_ASYNC16(st + F_KHI + off, Kh + (size_t)(n0 + r) * 128 + c * 32 + g * 8);
        CP_ASYNC16(st + F_KLO + off, Kl + (size_t)(n0 + r) * 128 + c * 32 + g * 8);
    }
#pragma unroll
    for (int it = 0; it < 4; it++) {            // Vt hi/lo: 128 rows x 64 cols
        int id = tid + it * 256;
        int r = id >> 3, cg = id & 7, c = cg >> 2, g = cg & 3;
        uint32_t off = (uint32_t)(c * 8192) + TOFF(r, g);
        CP_ASYNC16(st + F_VHI + off, Vh + (size_t)r * SEQ + n0 + c * 32 + g * 8);
        CP_ASYNC16(st + F_VLO + off, Vl + (size_t)r * SEQ + n0 + c * 32 + g * 8);
    }
}

__global__ __launch_bounds__(256) void flash_mma_kernel(
    const __nv_bfloat16* __restrict__ Qh, const __nv_bfloat16* __restrict__ Ql,
    const __nv_bfloat16* __restrict__ Kh, const __nv_bfloat16* __restrict__ Kl,
    const __nv_bfloat16* __restrict__ Vth, const __nv_bfloat16* __restrict__ Vtl,
    __nv_bfloat16* __restrict__ Ohi, __nv_bfloat16* __restrict__ Olo)
{
    extern __shared__ __align__(1024) char fsm[];
    uint32_t sb = smem_u32(fsm);
    const int tid = threadIdx.x, lane = tid & 31, wid = tid >> 5;
    const int warp_m = wid & 1, warp_n = wid >> 1;     // 2 x 4
    const int m0 = blockIdx.x * 64;
    const int bh = blockIdx.y, b = bh >> 5, h = bh & 31, kvh = h >> 2;
    const float scale = 0.08838834764831845f;

    const __nv_bfloat16* Qhp = Qh + ((size_t)(b * NHEADS + h) * SEQ + m0) * HDIM;
    const __nv_bfloat16* Qlp = Ql + ((size_t)(b * NHEADS + h) * SEQ + m0) * HDIM;
    const __nv_bfloat16* Khp = Kh + (size_t)(b * NKV + kvh) * SEQ * HDIM;
    const __nv_bfloat16* Klp = Kl + (size_t)(b * NKV + kvh) * SEQ * HDIM;
    const __nv_bfloat16* Vhp = Vth + (size_t)(b * NKV + kvh) * HDIM * SEQ;
    const __nv_bfloat16* Vlp = Vtl + (size_t)(b * NKV + kvh) * HDIM * SEQ;

    float* s_mi = (float*)(fsm + F_STAT);
    float* s_li = s_mi + 64;
    float* s_mn = s_mi + 128;
    float* s_al = s_mi + 192;
    float* s_pm = s_mi + 256;   // [64][4]
    float* s_ps = s_mi + 512;   // [64][4]
    if (tid < 64) { s_mi[tid] = -INFINITY; s_li[tid] = 0.f; }

    // Q resident load (hi+lo), grouped with stage 0
#pragma unroll
    for (int it = 0; it < 4; it++) {
        int id = tid + it * 256;
        int r = id >> 4, cg = id & 15, c = cg >> 2, g = cg & 3;
        uint32_t off = (uint32_t)(c * 4096) + TOFF(r, g);
        CP_ASYNC16(sb + F_QHI + off, Qhp + (size_t)r * 128 + c * 32 + g * 8);
        CP_ASYNC16(sb + F_QLO + off, Qlp + (size_t)r * 128 + c * 32 + g * 8);
    }
    flash_load_stage(sb + F_STG, tid, Khp, Klp, Vhp, Vlp, 0);
    CP_COMMIT();

    float acc_o[2][4][4];
#pragma unroll
    for (int mt = 0; mt < 2; mt++)
#pragma unroll
        for (int nf = 0; nf < 4; nf++)
#pragma unroll
            for (int q = 0; q < 4; q++) acc_o[mt][nf][q] = 0.f;

    const uint32_t aRow = warp_m * 32 + (lane & 15);       // + mt*16
    const int aG = lane >> 4;
    const uint32_t bRowS = warp_n * 16 + (lane & 7) + ((lane >> 4) & 1) * 8;
    const int bG = (lane >> 3) & 1;
    const int rl0b = warp_m * 32 + (lane >> 2);            // + mt*16, +8

    const int nb = m0 / 64 + 1;
    for (int j = 0; j < nb; j++) {
        uint32_t st = sb + F_STG + (uint32_t)(j & 1) * 65536;
        if (j + 1 < nb) {
            flash_load_stage(sb + F_STG + (uint32_t)((j + 1) & 1) * 65536, tid,
                             Khp, Klp, Vhp, Vlp, (j + 1) * 64);
            CP_COMMIT();
            CP_WAIT(1);
        } else {
            CP_WAIT(0);
        }
        __syncthreads();

        // ---- S = Q @ K^T (3-product split) ----
        float acc_s[2][2][4];
#pragma unroll
        for (int mt = 0; mt < 2; mt++)
#pragma unroll
            for (int nt = 0; nt < 2; nt++)
#pragma unroll
                for (int q = 0; q < 4; q++) acc_s[mt][nt][q] = 0.f;

#pragma unroll
        for (int s8 = 0; s8 < 8; s8++) {
            int kt = s8 >> 1, kh = s8 & 1;
            uint32_t ah[2][4], al[2][4];
#pragma unroll
            for (int mt = 0; mt < 2; mt++) {
                uint32_t r = aRow + mt * 16;
                uint32_t off = (uint32_t)(kt * 4096) + TOFF(r, kh * 2 + aG);
                LDSM_X4(ah[mt][0], ah[mt][1], ah[mt][2], ah[mt][3], sb + F_QHI + off);
                LDSM_X4(al[mt][0], al[mt][1], al[mt][2], al[mt][3], sb + F_QLO + off);
            }
            uint32_t kbh[4], kbl[4];
            uint32_t offb = (uint32_t)(kt * 4096) + TOFF(bRowS, kh * 2 + bG);
            LDSM_X4(kbh[0], kbh[1], kbh[2], kbh[3], st + F_KHI + offb);
            LDSM_X4(kbl[0], kbl[1], kbl[2], kbl[3], st + F_KLO + offb);
#pragma unroll
            for (int mt = 0; mt < 2; mt++)
#pragma unroll
                for (int nt = 0; nt < 2; nt++) {
                    MMA_BF16(acc_s[mt][nt], ah[mt], kbh + 2 * nt);
                    MMA_BF16(acc_s[mt][nt], ah[mt], kbl + 2 * nt);
                    MMA_BF16(acc_s[mt][nt], al[mt], kbh + 2 * nt);
                }
        }

        // ---- scale + causal mask + partial row max ----
        const bool diag = (j == nb - 1);
#pragma unroll
        for (int mt = 0; mt < 2; mt++) {
            int rl0 = rl0b + mt * 16;
            int qi0 = m0 + rl0, qi1 = qi0 + 8;
            float pm0 = -INFINITY, pm1 = -INFINITY;
#pragma unroll
            for (int nt = 0; nt < 2; nt++) {
                int c0 = j * 64 + warp_n * 16 + nt * 8 + (lane & 3) * 2;
                float v0 = acc_s[mt][nt][0] * scale;
                float v1 = acc_s[mt][nt][1] * scale;
                float v2 = acc_s[mt][nt][2] * scale;
                float v3 = acc_s[mt][nt][3] * scale;
                if (diag) {
                    if (c0     > qi0) v0 = -INFINITY;
                    if (c0 + 1 > qi0) v1 = -INFINITY;
                    if (c0     > qi1) v2 = -INFINITY;
                    if (c0 + 1 > qi1) v3 = -INFINITY;
                }
                acc_s[mt][nt][0] = v0; acc_s[mt][nt][1] = v1;
                acc_s[mt][nt][2] = v2; acc_s[mt][nt][3] = v3;
                pm0 = fmaxf(pm0, fmaxf(v0, v1));
                pm1 = fmaxf(pm1, fmaxf(v2, v3));
            }
            pm0 = fmaxf(pm0, __shfl_xor_sync(0xffffffffu, pm0, 1));
            pm0 = fmaxf(pm0, __shfl_xor_sync(0xffffffffu, pm0, 2));
            pm1 = fmaxf(pm1, __shfl_xor_sync(0xffffffffu, pm1, 1));
            pm1 = fmaxf(pm1, __shfl_xor_sync(0xffffffffu, pm1, 2));
            if ((lane & 3) == 0) {
                s_pm[rl0 * 4 + warp_n]       = pm0;
                s_pm[(rl0 + 8) * 4 + warp_n] = pm1;
            }
        }
        __syncthreads();
        if (tid < 64) {
            float m4 = fmaxf(fmaxf(s_pm[tid*4], s_pm[tid*4+1]),
                             fmaxf(s_pm[tid*4+2], s_pm[tid*4+3]));
            float mold = s_mi[tid];
            float mnew = fmaxf(mold, m4);
            s_mn[tid] = mnew;
            s_al[tid] = __expf(mold - mnew);
            s_mi[tid] = mnew;
        }
        __syncthreads();

        // ---- exp, write P hi/lo, rescale O, partial sums ----
#pragma unroll
        for (int mt = 0; mt < 2; mt++) {
            int rl0 = rl0b + mt * 16, rl1 = rl0 + 8;
            float mn0 = s_mn[rl0], mn1 = s_mn[rl1];
            float a0 = s_al[rl0],  a1 = s_al[rl1];
            float ps0 = 0.f, ps1 = 0.f;
#pragma unroll
            for (int nt = 0; nt < 2; nt++) {
                float p0 = __expf(acc_s[mt][nt][0] - mn0);
                float p1 = __expf(acc_s[mt][nt][1] - mn0);
                float p2 = __expf(acc_s[mt][nt][2] - mn1);
                float p3 = __expf(acc_s[mt][nt][3] - mn1);
                ps0 += p0 + p1; ps1 += p2 + p3;
                int c0 = warp_n * 16 + nt * 8 + (lane & 3) * 2;   // 0..63
                int ktile = c0 >> 5, cc = c0 & 31, g = cc >> 3;
                uint32_t bo = (uint32_t)((cc & 7) * 2);
                uint32_t o0 = (uint32_t)(ktile * 4096) + TOFF(rl0, g) + bo;
                uint32_t o1 = (uint32_t)(ktile * 4096) + TOFF(rl1, g) + bo;
                __nv_bfloat16 h0 = __float2bfloat16(p0), h1 = __float2bfloat16(p1);
                __nv_bfloat16 h2 = __float2bfloat16(p2), h3 = __float2bfloat16(p3);
                *(__nv_bfloat162*)(fsm + F_PHI + o0) = __nv_bfloat162{h0, h1};
                *(__nv_bfloat162*)(fsm + F_PHI + o1) = __nv_bfloat162{h2, h3};
                *(__nv_bfloat162*)(fsm + F_PLO + o0) = __nv_bfloat162{
                    __float2bfloat16(p0 - __bfloat162float(h0)),
                    __float2bfloat16(p1 - __bfloat162float(h1))};
                *(__nv_bfloat162*)(fsm + F_PLO + o1) = __nv_bfloat162{
                    __float2bfloat16(p2 - __bfloat162float(h2)),
                    __float2bfloat16(p3 - __bfloat162float(h3))};
            }
#pragma unroll
            for (int nf = 0; nf < 4; nf++) {
                acc_o[mt][nf][0] *= a0; acc_o[mt][nf][1] *= a0;
                acc_o[mt][nf][2] *= a1; acc_o[mt][nf][3] *= a1;
            }
            ps0 += __shfl_xor_sync(0xffffffffu, ps0, 1);
            ps0 += __shfl_xor_sync(0xffffffffu, ps0, 2);
            ps1 += __shfl_xor_sync(0xffffffffu, ps1, 1);
            ps1 += __shfl_xor_sync(0xffffffffu, ps1, 2);
            if ((lane & 3) == 0) {
                s_ps[rl0 * 4 + warp_n] = ps0;
                s_ps[rl1 * 4 + warp_n] = ps1;
            }
        }
        __syncthreads();
        if (tid < 64)
            s_li[tid] = s_li[tid] * s_al[tid] +
                        (s_ps[tid*4] + s_ps[tid*4+1] + s_ps[tid*4+2] + s_ps[tid*4+3]);

        // ---- O += P @ V ----
#pragma unroll
        for (int ks = 0; ks < 4; ks++) {
            int kt = ks >> 1, kh = ks & 1;
            uint32_t pah[2][4], pal[2][4];
#pragma unroll
            for (int mt = 0; mt < 2; mt++) {
                uint32_t r = aRow + mt * 16;
                uint32_t off = (uint32_t)(kt * 4096) + TOFF(r, kh * 2 + aG);
                LDSM_X4(pah[mt][0], pah[mt][1], pah[mt][2], pah[mt][3], sb + F_PHI + off);
                LDSM_X4(pal[mt][0], pal[mt][1], pal[mt][2], pal[mt][3], sb + F_PLO + off);
            }
#pragma unroll
            for (int p = 0; p < 2; p++) {
                uint32_t rv = warp_n * 32 + p * 16 + (lane & 7) + ((lane >> 4) & 1) * 8;
                uint32_t off = (uint32_t)(kt * 8192) + TOFF(rv, kh * 2 + bG);
                uint32_t vh_[4], vl_[4];
                LDSM_X4(vh_[0], vh_[1], vh_[2], vh_[3], st + F_VHI + off);
                LDSM_X4(vl_[0], vl_[1], vl_[2], vl_[3], st + F_VLO + off);
#pragma unroll
                for (int mt = 0; mt < 2; mt++)
#pragma unroll
                    for (int q = 0; q < 2; q++) {
                        int nf = p * 2 + q;
                        MMA_BF16(acc_o[mt][nf], pah[mt], vh_ + 2 * q);
                        MMA_BF16(acc_o[mt][nf], pah[mt], vl_ + 2 * q);
                        MMA_BF16(acc_o[mt][nf], pal[mt], vh_ + 2 * q);
                    }
            }
        }
        __syncthreads();   // protect stages + P for next iteration
    }

    // ---- epilogue: normalize, write O hi/lo [b*S+q][h*128+col] ----
#pragma unroll
    for (int mt = 0; mt < 2; mt++) {
        int rl0 = rl0b + mt * 16, rl1 = rl0 + 8;
        float inv0 = 1.f / s_li[rl0], inv1 = 1.f / s_li[rl1];
        size_t row0 = (size_t)(b * SEQ + m0 + rl0) * DMODEL;
        size_t row1 = (size_t)(b * SEQ + m0 + rl1) * DMODEL;
#pragma unroll
        for (int nf = 0; nf < 4; nf++) {
            int col = h * 128 + warp_n * 32 + nf * 8 + (lane & 3) * 2;
            float o00 = acc_o[mt][nf][0] * inv0, o01 = acc_o[mt][nf][1] * inv0;
            float o10 = acc_o[mt][nf][2] * inv1, o11 = acc_o[mt][nf][3] * inv1;
            __nv_bfloat16 h00 = __float2bfloat16(o00), h01 = __float2bfloat16(o01);
            __nv_bfloat16 h10 = __float2bfloat16(o10), h11 = __float2bfloat16(o11);
            *(__nv_bfloat162*)(Ohi + row0 + col) = __nv_bfloat162{h00, h01};
            *(__nv_bfloat162*)(Ohi + row1 + col) = __nv_bfloat162{h10, h11};
            *(__nv_bfloat162*)(Olo + row0 + col) = __nv_bfloat162{
                __float2bfloat16(o00 - __bfloat162float(h00)),
                __float2bfloat16(o01 - __bfloat162float(h01))};
            *(__nv_bfloat162*)(Olo + row1 + col) = __nv_bfloat162{
                __float2bfloat16(o10 - __bfloat162float(h10)),
                __float2bfloat16(o11 - __bfloat162float(h11))};
        }
    }
}

// ---------------- launch ----------------------------------------------------
extern "C" void kernel_launch(void* const* d_in, const int* in_sizes, int n_in,
                              void* d_out, int out_size)
{
    (void)in_sizes; (void)n_in; (void)out_size;
    const float* x  = (const float*)d_in[0];
    const float* Wq = (const float*)d_in[2];
    const float* Wk = (const float*)d_in[3];
    const float* Wv = (const float*)d_in[4];
    const float* Wo = (const float*)d_in[5];
    float* out = (float*)d_out;

    float *rawQ, *rawK, *rawV, *cosT, *sinT;
    __nv_bfloat16 *xhi, *xlo, *Ohi, *Olo, *Qhi, *Qlo, *Khi, *Klo, *Vth, *Vtl;
    __nv_bfloat16 *Wqh, *Wql, *Wkh, *Wkl, *Wvh, *Wvl, *Woh, *Wol;
    cudaGetSymbolAddress((void**)&rawQ, g_rawQ);
    cudaGetSymbolAddress((void**)&rawK, g_rawK);
    cudaGetSymbolAddress((void**)&rawV, g_rawV);
    cudaGetSymbolAddress((void**)&cosT, g_cosT);
    cudaGetSymbolAddress((void**)&sinT, g_sinT);
    cudaGetSymbolAddress((void**)&xhi,  g_xhi);
    cudaGetSymbolAddress((void**)&xlo,  g_xlo);
    cudaGetSymbolAddress((void**)&Ohi,  g_Ohi);
    cudaGetSymbolAddress((void**)&Olo,  g_Olo);
    cudaGetSymbolAddress((void**)&Qhi,  g_Qhi);
    cudaGetSymbolAddress((void**)&Qlo,  g_Qlo);
    cudaGetSymbolAddress((void**)&Khi,  g_Khi);
    cudaGetSymbolAddress((void**)&Klo,  g_Klo);
    cudaGetSymbolAddress((void**)&Vth,  g_Vth);
    cudaGetSymbolAddress((void**)&Vtl,  g_Vtl);
    cudaGetSymbolAddress((void**)&Wqh,  g_Wqt_h);
    cudaGetSymbolAddress((void**)&Wql,  g_Wqt_l);
    cudaGetSymbolAddress((void**)&Wkh,  g_Wkt_h);
    cudaGetSymbolAddress((void**)&Wkl,  g_Wkt_l);
    cudaGetSymbolAddress((void**)&Wvh,  g_Wvt_h);
    cudaGetSymbolAddress((void**)&Wvl,  g_Wvt_l);
    cudaGetSymbolAddress((void**)&Woh,  g_Wot_h);
    cudaGetSymbolAddress((void**)&Wol,  g_Wot_l);

    cudaFuncSetAttribute(gemm_mma_kernel, cudaFuncAttributeMaxDynamicSharedMemorySize, GEMM_SMEM);
    cudaFuncSetAttribute(flash_mma_kernel, cudaFuncAttributeMaxDynamicSharedMemorySize, F_SMEM);

    // operand prep
    split_kernel<<<((size_t)MROWS * DMODEL / 4) / 256, 256>>>(x, xhi, xlo);
    transpose_split_kernel<<<dim3(DMODEL/32, DMODEL/32), 256>>>(Wq, Wqh, Wql, DMODEL, DMODEL);
    transpose_split_kernel<<<dim3(KVW/32,    DMODEL/32), 256>>>(Wk, Wkh, Wkl, DMODEL, KVW);
    transpose_split_kernel<<<dim3(KVW/32,    DMODEL/32), 256>>>(Wv, Wvh, Wvl, DMODEL, KVW);
    transpose_split_kernel<<<dim3(DMODEL/32, DMODEL/32), 256>>>(Wo, Woh, Wol, DMODEL, DMODEL);
    rope_table_kernel<<<(SEQ * 64) / 256, 256>>>(cosT, sinT);

    // QKV projections
    gemm_mma_kernel<<<dim3(DMODEL/128, MROWS/128), 256, GEMM_SMEM>>>(xhi, xlo, Wqh, Wql, rawQ, DMODEL);
    gemm_mma_kernel<<<dim3(KVW/128,    MROWS/128), 256, GEMM_SMEM>>>(xhi, xlo, Wkh, Wkl, rawK, KVW);
    gemm_mma_kernel<<<dim3(KVW/128,    MROWS/128), 256, GEMM_SMEM>>>(xhi, xlo, Wvh, Wvl, rawV, KVW);

    // RoPE + relayout to bf16 hi/lo; V transpose-split
    rope_split_kernel<<<(BATCH * NHEADS * SEQ * 64) / 256, 256>>>(rawQ, Qhi, Qlo, NHEADS, cosT, sinT);
    rope_split_kernel<<<(BATCH * NKV    * SEQ * 64) / 256, 256>>>(rawK, Khi, Klo, NKV, cosT, sinT);
    vtrans_split_kernel<<<dim3(SEQ/32, HDIM/32, BATCH*NKV), 256>>>(rawV, Vth, Vtl);

    // tensor-core causal flash attention
    flash_mma_kernel<<<dim3(SEQ/64, BATCH*NHEADS), 256, F_SMEM>>>(
        Qhi, Qlo, Khi, Klo, Vth, Vtl, Ohi, Olo);

    // output projection
    gemm_mma_kernel<<<dim3(DMODEL/128, MROWS/128), 256, GEMM_SMEM>>>(Ohi, Olo, Woh, Wol, out, DMODEL);
}

// round 8
// speedup vs baseline: 4.9694x; 1.0317x over previous
#include <cuda_runtime.h>
#include <cuda_bf16.h>
#include <math.h>
#include <stdint.h>

#define BATCH  2
#define SEQ    2048
#define DMODEL 4096
#define NHEADS 32
#define NKV    8
#define HDIM   128
#define MROWS  (BATCH*SEQ)        // 4096
#define KVW    (NKV*HDIM)         // 1024
#define NQKV   (DMODEL + 2*KVW)   // 6144

// ---------------- scratch (static device buffers; no cudaMalloc) -----------
__device__ __align__(256) float g_rawQKV[(size_t)MROWS * NQKV];   // [Q|K|V] fused proj

__device__ __align__(256) __nv_bfloat16 g_xhi[(size_t)MROWS * DMODEL];
__device__ __align__(256) __nv_bfloat16 g_xlo[(size_t)MROWS * DMODEL];
__device__ __align__(256) __nv_bfloat16 g_Ohi[(size_t)MROWS * DMODEL];
__device__ __align__(256) __nv_bfloat16 g_Olo[(size_t)MROWS * DMODEL];
__device__ __align__(256) __nv_bfloat16 g_Qhi[(size_t)MROWS * DMODEL];
__device__ __align__(256) __nv_bfloat16 g_Qlo[(size_t)MROWS * DMODEL];
__device__ __align__(256) __nv_bfloat16 g_Khi[(size_t)MROWS * KVW];
__device__ __align__(256) __nv_bfloat16 g_Klo[(size_t)MROWS * KVW];
__device__ __align__(256) __nv_bfloat16 g_Vth[(size_t)MROWS * KVW];
__device__ __align__(256) __nv_bfloat16 g_Vtl[(size_t)MROWS * KVW];
// concat transposed weights [Wq; Wk; Wv] = [NQKV, DMODEL] bf16 hi/lo
__device__ __align__(256) __nv_bfloat16 g_Wqkvt_h[(size_t)NQKV * DMODEL];
__device__ __align__(256) __nv_bfloat16 g_Wqkvt_l[(size_t)NQKV * DMODEL];
__device__ __align__(256) __nv_bfloat16 g_Wot_h[(size_t)DMODEL * DMODEL];
__device__ __align__(256) __nv_bfloat16 g_Wot_l[(size_t)DMODEL * DMODEL];
__device__ __align__(256) float g_cosT[SEQ * 64];
__device__ __align__(256) float g_sinT[SEQ * 64];

// ---------------- PTX helpers ----------------------------------------------
__device__ __forceinline__ uint32_t smem_u32(const void* p) {
    uint32_t a;
    asm("{ .reg .u64 t; cvta.to.shared.u64 t, %1; cvt.u32.u64 %0, t; }" : "=r"(a) : "l"(p));
    return a;
}

#define CP_ASYNC16(dst, src) \
    asm volatile("cp.async.cg.shared.global [%0], [%1], 16;" :: "r"(dst), "l"(src) : "memory")
#define CP_COMMIT() asm volatile("cp.async.commit_group;" ::: "memory")
#define CP_WAIT(n)  asm volatile("cp.async.wait_group %0;" :: "n"(n) : "memory")

#define LDSM_X4(r0, r1, r2, r3, addr) \
    asm volatile("ldmatrix.sync.aligned.m8n8.x4.shared.b16 {%0,%1,%2,%3}, [%4];" \
        : "=r"(r0), "=r"(r1), "=r"(r2), "=r"(r3) : "r"(addr))

#define MMA_BF16(d, a, b) \
    asm volatile("mma.sync.aligned.m16n8k16.row.col.f32.bf16.bf16.f32 " \
        "{%0,%1,%2,%3}, {%4,%5,%6,%7}, {%8,%9}, {%0,%1,%2,%3};" \
        : "+f"((d)[0]), "+f"((d)[1]), "+f"((d)[2]), "+f"((d)[3]) \
        : "r"((a)[0]), "r"((a)[1]), "r"((a)[2]), "r"((a)[3]), \
          "r"((b)[0]), "r"((b)[1]))

// chunk-tile addressing (validated R4): row r = 64B as four 16B groups,
// group g at ((g ^ ((r>>1)&3)) << 4)
#define TOFF(r, g) ((uint32_t)((r) * 64 + ((((g) ^ (((r) >> 1) & 3))) << 4)))

__device__ __forceinline__ void split_pack(float p0, float p1,
                                           uint32_t& hi, uint32_t& lo) {
    __nv_bfloat162 h{__float2bfloat16(p0), __float2bfloat16(p1)};
    hi = *reinterpret_cast<uint32_t*>(&h);
    __nv_bfloat162 l{__float2bfloat16(p0 - __bfloat162float(h.x)),
                     __float2bfloat16(p1 - __bfloat162float(h.y))};
    lo = *reinterpret_cast<uint32_t*>(&l);
}

// ---------------- conversion kernels ---------------------------------------
__global__ __launch_bounds__(256) void split_kernel(
    const float* __restrict__ X, __nv_bfloat16* __restrict__ H,
    __nv_bfloat16* __restrict__ L)
{
    size_t i = (size_t)blockIdx.x * 256 + threadIdx.x;
    float4 v = reinterpret_cast<const float4*>(X)[i];
    float a[4] = {v.x, v.y, v.z, v.w};
    __nv_bfloat162* H2 = reinterpret_cast<__nv_bfloat162*>(H);
    __nv_bfloat162* L2 = reinterpret_cast<__nv_bfloat162*>(L);
#pragma unroll
    for (int p = 0; p < 2; p++) {
        __nv_bfloat16 h0 = __float2bfloat16(a[p*2+0]);
        __nv_bfloat16 h1 = __float2bfloat16(a[p*2+1]);
        __nv_bfloat16 l0 = __float2bfloat16(a[p*2+0] - __bfloat162float(h0));
        __nv_bfloat16 l1 = __float2bfloat16(a[p*2+1] - __bfloat162float(h1));
        H2[i*2 + p] = __nv_bfloat162{h0, h1};
        L2[i*2 + p] = __nv_bfloat162{l0, l1};
    }
}

__global__ __launch_bounds__(256) void transpose_split_kernel(
    const float* __restrict__ W, __nv_bfloat16* __restrict__ Th,
    __nv_bfloat16* __restrict__ Tl, int K, int N)
{
    __shared__ float tile[32][33];
    int n0 = blockIdx.x * 32, k0 = blockIdx.y * 32;
    int tx = threadIdx.x & 31, ty = threadIdx.x >> 5;
#pragma unroll
    for (int j = 0; j < 32; j += 8)
        tile[ty + j][tx] = W[(size_t)(k0 + ty + j) * N + n0 + tx];
    __syncthreads();
#pragma unroll
    for (int j = 0; j < 32; j += 8) {
        float v = tile[tx][ty + j];
        __nv_bfloat16 h = __float2bfloat16(v);
        __nv_bfloat16 l = __float2bfloat16(v - __bfloat162float(h));
        size_t o = (size_t)(n0 + ty + j) * K + k0 + tx;
        Th[o] = h; Tl[o] = l;
    }
}

// V slice of rawQKV -> Vt hi/lo [B*KV, HDIM, SEQ]
__global__ __launch_bounds__(256) void vtrans_split_kernel(
    const float* __restrict__ raw, __nv_bfloat16* __restrict__ Th,
    __nv_bfloat16* __restrict__ Tl)
{
    __shared__ float tile[32][33];
    int s0 = blockIdx.x * 32, d0 = blockIdx.y * 32, bkv = blockIdx.z;
    int b = bkv >> 3, kvh = bkv & 7;
    int tx = threadIdx.x & 31, ty = threadIdx.x >> 5;
#pragma unroll
    for (int j = 0; j < 32; j += 8)
        tile[ty + j][tx] = raw[((size_t)(b * SEQ) + s0 + ty + j) * NQKV +
                               (DMODEL + KVW) + kvh * HDIM + d0 + tx];
    __syncthreads();
#pragma unroll
    for (int j = 0; j < 32; j += 8) {
        float v = tile[tx][ty + j];
        __nv_bfloat16 h = __float2bfloat16(v);
        __nv_bfloat16 l = __float2bfloat16(v - __bfloat162float(h));
        size_t o = ((size_t)bkv * HDIM + d0 + ty + j) * SEQ + s0 + tx;
        Th[o] = h; Tl[o] = l;
    }
}

// ---------------- RoPE table + apply ---------------------------------------
__global__ __launch_bounds__(256) void rope_table_kernel(
    float* __restrict__ cosT, float* __restrict__ sinT)
{
    int idx = blockIdx.x * 256 + threadIdx.x;
    int d2 = idx & 63, s = idx >> 6;
    float invf = expf(-(float)d2 * (9.210340371976184f / 64.0f));
    float ang  = (float)s * invf;
    double sv, cv;
    sincos((double)ang, &sv, &cv);
    cosT[idx] = (float)cv;
    sinT[idx] = (float)sv;
}

__global__ __launch_bounds__(256) void rope_split_kernel(
    const float* __restrict__ raw, __nv_bfloat16* __restrict__ Oh,
    __nv_bfloat16* __restrict__ Ol, int nheads, int colbase,
    const float* __restrict__ cosT, const float* __restrict__ sinT)
{
    int idx = blockIdx.x * 256 + threadIdx.x;
    int d2 = idx & 63;
    int t  = idx >> 6;
    int s  = t & (SEQ - 1);
    t >>= 11;
    int h = t % nheads;
    int b = t / nheads;
    if (b >= BATCH) return;

    const float* row = raw + ((size_t)(b * SEQ + s)) * NQKV + colbase + h * HDIM;
    float x0 = row[d2], x1 = row[d2 + 64];
    float c  = cosT[s * 64 + d2];
    float sn = sinT[s * 64 + d2];
    float o0 = x0 * c - x1 * sn;
    float o1 = x1 * c + x0 * sn;
    size_t ob = ((size_t)((b * nheads + h) * SEQ + s)) * HDIM;
    __nv_bfloat16 h0 = __float2bfloat16(o0);
    __nv_bfloat16 h1 = __float2bfloat16(o1);
    Oh[ob + d2]      = h0;
    Oh[ob + d2 + 64] = h1;
    Ol[ob + d2]      = __float2bfloat16(o0 - __bfloat162float(h0));
    Ol[ob + d2 + 64] = __float2bfloat16(o1 - __bfloat162float(h1));
}

// ---------------- mma.sync split-bf16 GEMM (validated R4) ------------------
#define GEMM_SMEM (2 * 32768)

__device__ __forceinline__ void load_stage(
    uint32_t sb, int tid,
    const __nv_bfloat16* __restrict__ Ahi, const __nv_bfloat16* __restrict__ Alo,
    const __nv_bfloat16* __restrict__ Bhi, const __nv_bfloat16* __restrict__ Blo,
    int m0, int n0, int k0)
{
#pragma unroll
    for (int it = 0; it < 8; it++) {
        int id = tid + it * 256;
        int mat = id >> 9;
        int w = id & 511;
        int r = w >> 2, c = w & 3;
        uint32_t so = sb + mat * 8192 + r * 64 + (((c ^ ((r >> 1) & 3))) << 4);
        const __nv_bfloat16* src;
        if      (mat == 0) src = Ahi + (size_t)(m0 + r) * 4096 + k0 + c * 8;
        else if (mat == 1) src = Alo + (size_t)(m0 + r) * 4096 + k0 + c * 8;
        else if (mat == 2) src = Bhi + (size_t)(n0 + r) * 4096 + k0 + c * 8;
        else               src = Blo + (size_t)(n0 + r) * 4096 + k0 + c * 8;
        CP_ASYNC16(so, src);
    }
}

__global__ __launch_bounds__(256) void gemm_mma_kernel(
    const __nv_bfloat16* __restrict__ Ahi, const __nv_bfloat16* __restrict__ Alo,
    const __nv_bfloat16* __restrict__ Bhi, const __nv_bfloat16* __restrict__ Blo,
    float* __restrict__ C, int N)
{
    extern __shared__ __align__(1024) char smem[];
    uint32_t sb = smem_u32(smem);
    const int tid = threadIdx.x;
    const int lane = tid & 31, wid = tid >> 5;
    const int warp_m = wid & 3, warp_n = wid >> 2;
    const int m0 = blockIdx.y * 128, n0 = blockIdx.x * 128;

    float acc[2][8][4];
#pragma unroll
    for (int mt = 0; mt < 2; mt++)
#pragma unroll
        for (int nt = 0; nt < 8; nt++)
#pragma unroll
            for (int q = 0; q < 4; q++) acc[mt][nt][q] = 0.f;

    load_stage(sb, tid, Ahi, Alo, Bhi, Blo, m0, n0, 0);
    CP_COMMIT();

    const uint32_t aRowB = warp_m * 32 + (lane & 15);
    const int aKh = lane >> 4;
    const uint32_t bRowB = warp_n * 64 + (lane & 7) + ((lane >> 4) & 1) * 8;
    const int bKh = (lane >> 3) & 1;

    for (int kb = 0; kb < 128; kb++) {
        const uint32_t s_off = (uint32_t)(kb & 1) * 32768;
        if (kb + 1 < 128) {
            load_stage(sb + ((kb + 1) & 1) * 32768, tid, Ahi, Alo, Bhi, Blo,
                       m0, n0, (kb + 1) * 32);
            CP_COMMIT();
            CP_WAIT(1);
        } else {
            CP_WAIT(0);
        }
        __syncthreads();

#pragma unroll
        for (int kk = 0; kk < 2; kk++) {
            uint32_t ah[2][4], al[2][4];
#pragma unroll
            for (int mt = 0; mt < 2; mt++) {
                uint32_t r = aRowB + mt * 16;
                uint32_t chunk = (uint32_t)(kk * 2 + aKh);
                uint32_t off = r * 64 + ((chunk ^ ((r >> 1) & 3)) << 4);
                LDSM_X4(ah[mt][0], ah[mt][1], ah[mt][2], ah[mt][3], sb + s_off + off);
                LDSM_X4(al[mt][0], al[mt][1], al[mt][2], al[mt][3], sb + s_off + 8192 + off);
            }
#pragma unroll
            for (int p = 0; p < 4; p++) {
                uint32_t r = bRowB + p * 16;
                uint32_t chunk = (uint32_t)(kk * 2 + bKh);
                uint32_t off = r * 64 + ((chunk ^ ((r >> 1) & 3)) << 4);
                uint32_t bh[4], bl[4];
                LDSM_X4(bh[0], bh[1], bh[2], bh[3], sb + s_off + 16384 + off);
                LDSM_X4(bl[0], bl[1], bl[2], bl[3], sb + s_off + 24576 + off);
#pragma unroll
                for (int mt = 0; mt < 2; mt++) {
                    MMA_BF16(acc[mt][2*p],     ah[mt], bh + 0);
                    MMA_BF16(acc[mt][2*p],     ah[mt], bl + 0);
                    MMA_BF16(acc[mt][2*p],     al[mt], bh + 0);
                    MMA_BF16(acc[mt][2*p + 1], ah[mt], bh + 2);
                    MMA_BF16(acc[mt][2*p + 1], ah[mt], bl + 2);
                    MMA_BF16(acc[mt][2*p + 1], al[mt], bh + 2);
                }
            }
        }
        __syncthreads();
    }

#pragma unroll
    for (int mt = 0; mt < 2; mt++) {
        int row = m0 + warp_m * 32 + mt * 16 + (lane >> 2);
#pragma unroll
        for (int nt = 0; nt < 8; nt++) {
            int col = n0 + warp_n * 64 + nt * 8 + (lane & 3) * 2;
            *reinterpret_cast<float2*>(C + (size_t)row * N + col) =
                float2{acc[mt][nt][0], acc[mt][nt][1]};
            *reinterpret_cast<float2*>(C + (size_t)(row + 8) * N + col) =
                float2{acc[mt][nt][2], acc[mt][nt][3]};
        }
    }
}

// ---------------- flash attention: register-P, 128q x 64kv -----------------
// 8 warps, each owns 16 q rows x full 64 kv. P stays in registers (fragment
// identity C(m16n8 pair) == A(m16k16)). mi/li in registers, quad shuffles.
#define F_QHI  0
#define F_QLO  32768
#define F_STG  65536            /* + stage*65536 */
#define FS_KHI 0
#define FS_KLO 16384
#define FS_VHI 32768
#define FS_VLO 49152
#define F_SMEM (65536 + 2 * 65536)   /* 192 KB */

__device__ __forceinline__ void flash_load_stage(
    uint32_t st, int tid,
    const __nv_bfloat16* __restrict__ Kh, const __nv_bfloat16* __restrict__ Kl,
    const __nv_bfloat16* __restrict__ Vh, const __nv_bfloat16* __restrict__ Vl,
    int n0)
{
#pragma unroll
    for (int it = 0; it < 4; it++) {            // K hi/lo: 64 rows x 128 k
        int id = tid + it * 256;
        int r = id >> 4, cg = id & 15, kt = cg >> 2, g = cg & 3;
        uint32_t off = (uint32_t)(kt * 4096) + TOFF(r, g);
        CP_ASYNC16(st + FS_KHI + off, Kh + (size_t)(n0 + r) * 128 + kt * 32 + g * 8);
        CP_ASYNC16(st + FS_KLO + off, Kl + (size_t)(n0 + r) * 128 + kt * 32 + g * 8);
    }
#pragma unroll
    for (int it = 0; it < 4; it++) {            // Vt hi/lo: 128 rows x 64 kv
        int id = tid + it * 256;
        int r = id >> 3, cg = id & 7, kt = cg >> 2, g = cg & 3;
        uint32_t off = (uint32_t)(kt * 8192) + TOFF(r, g);
        CP_ASYNC16(st + FS_VHI + off, Vh + (size_t)r * SEQ + n0 + kt * 32 + g * 8);
        CP_ASYNC16(st + FS_VLO + off, Vl + (size_t)r * SEQ + n0 + kt * 32 + g * 8);
    }
}

__global__ __launch_bounds__(256, 1) void flash_mma_kernel(
    const __nv_bfloat16* __restrict__ Qh, const __nv_bfloat16* __restrict__ Ql,
    const __nv_bfloat16* __restrict__ Kh, const __nv_bfloat16* __restrict__ Kl,
    const __nv_bfloat16* __restrict__ Vth, const __nv_bfloat16* __restrict__ Vtl,
    __nv_bfloat16* __restrict__ Ohi, __nv_bfloat16* __restrict__ Olo)
{
    extern __shared__ __align__(1024) char fsm[];
    uint32_t sb = smem_u32(fsm);
    const int tid = threadIdx.x, lane = tid & 31, w = tid >> 5;
    const int mblk = gridDim.x - 1 - blockIdx.x;     // heavy CTAs first
    const int m0 = mblk * 128;
    const int bh = blockIdx.y, b = bh >> 5, h = bh & 31, kvh = h >> 2;
    const float scale = 0.08838834764831845f;

    const __nv_bfloat16* Qhp = Qh + ((size_t)(b * NHEADS + h) * SEQ + m0) * HDIM;
    const __nv_bfloat16* Qlp = Ql + ((size_t)(b * NHEADS + h) * SEQ + m0) * HDIM;
    const __nv_bfloat16* Khp = Kh + (size_t)(b * NKV + kvh) * SEQ * HDIM;
    const __nv_bfloat16* Klp = Kl + (size_t)(b * NKV + kvh) * SEQ * HDIM;
    const __nv_bfloat16* Vhp = Vth + (size_t)(b * NKV + kvh) * HDIM * SEQ;
    const __nv_bfloat16* Vlp = Vtl + (size_t)(b * NKV + kvh) * HDIM * SEQ;

    // Q resident: 128 rows x 128 k, hi/lo (grouped with stage 0)
#pragma unroll
    for (int it = 0; it < 8; it++) {
        int id = tid + it * 256;
        int r = id >> 4, cg = id & 15, kt = cg >> 2, g = cg & 3;
        uint32_t off = (uint32_t)(kt * 8192) + TOFF(r, g);
        CP_ASYNC16(sb + F_QHI + off, Qhp + (size_t)r * 128 + kt * 32 + g * 8);
        CP_ASYNC16(sb + F_QLO + off, Qlp + (size_t)r * 128 + kt * 32 + g * 8);
    }
    flash_load_stage(sb + F_STG, tid, Khp, Klp, Vhp, Vlp, 0);
    CP_COMMIT();

    float acc_o[16][4];
#pragma unroll
    for (int nf = 0; nf < 16; nf++)
#pragma unroll
        for (int q = 0; q < 4; q++) acc_o[nf][q] = 0.f;
    float mi0 = -INFINITY, mi1 = -INFINITY, li0 = 0.f, li1 = 0.f;

    const uint32_t aRow = (uint32_t)(w * 16 + (lane & 15));
    const int aG = lane >> 4;
    const uint32_t bLn = (uint32_t)((lane & 7) + ((lane >> 4) & 1) * 8);
    const int bG = (lane >> 3) & 1;
    const int r0 = w * 16 + (lane >> 2);             // local q row; +8 second

    const int nb = 2 * mblk + 2;
    for (int j = 0; j < nb; j++) {
        uint32_t st = sb + F_STG + (uint32_t)(j & 1) * 65536;
        if (j + 1 < nb) {
            flash_load_stage(sb + F_STG + (uint32_t)((j + 1) & 1) * 65536, tid,
                             Khp, Klp, Vhp, Vlp, (j + 1) * 64);
            CP_COMMIT();
            CP_WAIT(1);
        } else {
            CP_WAIT(0);
        }
        __syncthreads();

        // ---- S = Q @ K^T (3-product), warp-private 16x64 ----
        float s[8][4];
#pragma unroll
        for (int nt = 0; nt < 8; nt++)
#pragma unroll
            for (int q = 0; q < 4; q++) s[nt][q] = 0.f;

#pragma unroll
        for (int ks = 0; ks < 8; ks++) {
            int kt = ks >> 1, kh = ks & 1;
            uint32_t ah[4], al[4];
            uint32_t offA = (uint32_t)(kt * 8192) + TOFF(aRow, kh * 2 + aG);
            LDSM_X4(ah[0], ah[1], ah[2], ah[3], sb + F_QHI + offA);
            LDSM_X4(al[0], al[1], al[2], al[3], sb + F_QLO + offA);
#pragma unroll
            for (int np = 0; np < 4; np++) {
                uint32_t offB = (uint32_t)(kt * 4096) + TOFF(np * 16 + bLn, kh * 2 + bG);
                uint32_t kbh[4], kbl[4];
                LDSM_X4(kbh[0], kbh[1], kbh[2], kbh[3], st + FS_KHI + offB);
                LDSM_X4(kbl[0], kbl[1], kbl[2], kbl[3], st + FS_KLO + offB);
                MMA_BF16(s[2*np],     ah, kbh + 0);
                MMA_BF16(s[2*np],     ah, kbl + 0);
                MMA_BF16(s[2*np],     al, kbh + 0);
                MMA_BF16(s[2*np + 1], ah, kbh + 2);
                MMA_BF16(s[2*np + 1], ah, kbl + 2);
                MMA_BF16(s[2*np + 1], al, kbh + 2);
            }
        }

        // ---- scale + causal mask + register softmax ----
        const bool diag = (j >= nb - 2);
        const int qi0 = m0 + r0, qi1 = qi0 + 8;
        float pm0 = -INFINITY, pm1 = -INFINITY;
#pragma unroll
        for (int nt = 0; nt < 8; nt++) {
            int c0 = j * 64 + nt * 8 + (lane & 3) * 2;
            float v0 = s[nt][0] * scale, v1 = s[nt][1] * scale;
            float v2 = s[nt][2] * scale, v3 = s[nt][3] * scale;
            if (diag) {
                if (c0     > qi0) v0 = -INFINITY;
                if (c0 + 1 > qi0) v1 = -INFINITY;
                if (c0     > qi1) v2 = -INFINITY;
                if (c0 + 1 > qi1) v3 = -INFINITY;
            }
            s[nt][0] = v0; s[nt][1] = v1; s[nt][2] = v2; s[nt][3] = v3;
            pm0 = fmaxf(pm0, fmaxf(v0, v1));
            pm1 = fmaxf(pm1, fmaxf(v2, v3));
        }
        pm0 = fmaxf(pm0, __shfl_xor_sync(0xffffffffu, pm0, 1));
        pm0 = fmaxf(pm0, __shfl_xor_sync(0xffffffffu, pm0, 2));
        pm1 = fmaxf(pm1, __shfl_xor_sync(0xffffffffu, pm1, 1));
        pm1 = fmaxf(pm1, __shfl_xor_sync(0xffffffffu, pm1, 2));

        float mn0 = fmaxf(mi0, pm0), mn1 = fmaxf(mi1, pm1);
        float a0 = __expf(mi0 - mn0), a1 = __expf(mi1 - mn1);
        mi0 = mn0; mi1 = mn1;

        float ps0 = 0.f, ps1 = 0.f;
#pragma unroll
        for (int nt = 0; nt < 8; nt++) {
            float p0 = __expf(s[nt][0] - mn0);
            float p1 = __expf(s[nt][1] - mn0);
            float p2 = __expf(s[nt][2] - mn1);
            float p3 = __expf(s[nt][3] - mn1);
            s[nt][0] = p0; s[nt][1] = p1; s[nt][2] = p2; s[nt][3] = p3;
            ps0 += p0 + p1; ps1 += p2 + p3;
        }
        ps0 += __shfl_xor_sync(0xffffffffu, ps0, 1);
        ps0 += __shfl_xor_sync(0xffffffffu, ps0, 2);
        ps1 += __shfl_xor_sync(0xffffffffu, ps1, 1);
        ps1 += __shfl_xor_sync(0xffffffffu, ps1, 2);
        li0 = li0 * a0 + ps0;
        li1 = li1 * a1 + ps1;

#pragma unroll
        for (int nf = 0; nf < 16; nf++) {
            acc_o[nf][0] *= a0; acc_o[nf][1] *= a0;
            acc_o[nf][2] *= a1; acc_o[nf][3] *= a1;
        }

        // ---- O += P @ V  (P converted fragment-to-fragment in registers) ----
#pragma unroll
        for (int kt2 = 0; kt2 < 4; kt2++) {
            uint32_t pah[4], pal[4];
            split_pack(s[2*kt2][0],     s[2*kt2][1],     pah[0], pal[0]);
            split_pack(s[2*kt2][2],     s[2*kt2][3],     pah[1], pal[1]);
            split_pack(s[2*kt2 + 1][0], s[2*kt2 + 1][1], pah[2], pal[2]);
            split_pack(s[2*kt2 + 1][2], s[2*kt2 + 1][3], pah[3], pal[3]);
            int ktV = kt2 >> 1, khV = kt2 & 1;
#pragma unroll
            for (int np = 0; np < 8; np++) {
                uint32_t offV = (uint32_t)(ktV * 8192) + TOFF(np * 16 + bLn, khV * 2 + bG);
                uint32_t vh_[4], vl_[4];
                LDSM_X4(vh_[0], vh_[1], vh_[2], vh_[3], st + FS_VHI + offV);
                LDSM_X4(vl_[0], vl_[1], vl_[2], vl_[3], st + FS_VLO + offV);
                MMA_BF16(acc_o[2*np],     pah, vh_ + 0);
                MMA_BF16(acc_o[2*np],     pah, vl_ + 0);
                MMA_BF16(acc_o[2*np],     pal, vh_ + 0);
                MMA_BF16(acc_o[2*np + 1], pah, vh_ + 2);
                MMA_BF16(acc_o[2*np + 1], pah, vl_ + 2);
                MMA_BF16(acc_o[2*np + 1], pal, vh_ + 2);
            }
        }
        __syncthreads();   // protect stage buffers for refill
    }

    // ---- epilogue ----
    float inv0 = 1.f / li0, inv1 = 1.f / li1;
    size_t row0 = (size_t)(b * SEQ + m0 + r0) * DMODEL;
    size_t row1 = (size_t)(b * SEQ + m0 + r0 + 8) * DMODEL;
#pragma unroll
    for (int nf = 0; nf < 16; nf++) {
        int col = h * 128 + nf * 8 + (lane & 3) * 2;
        float o00 = acc_o[nf][0] * inv0, o01 = acc_o[nf][1] * inv0;
        float o10 = acc_o[nf][2] * inv1, o11 = acc_o[nf][3] * inv1;
        __nv_bfloat16 h00 = __float2bfloat16(o00), h01 = __float2bfloat16(o01);
        __nv_bfloat16 h10 = __float2bfloat16(o10), h11 = __float2bfloat16(o11);
        *(__nv_bfloat162*)(Ohi + row0 + col) = __nv_bfloat162{h00, h01};
        *(__nv_bfloat162*)(Ohi + row1 + col) = __nv_bfloat162{h10, h11};
        *(__nv_bfloat162*)(Olo + row0 + col) = __nv_bfloat162{
            __float2bfloat16(o00 - __bfloat162float(h00)),
            __float2bfloat16(o01 - __bfloat162float(h01))};
        *(__nv_bfloat162*)(Olo + row1 + col) = __nv_bfloat162{
            __float2bfloat16(o10 - __bfloat162float(h10)),
            __float2bfloat16(o11 - __bfloat162float(h11))};
    }
}

// ---------------- launch ----------------------------------------------------
extern "C" void kernel_launch(void* const* d_in, const int* in_sizes, int n_in,
                              void* d_out, int out_size)
{
    (void)in_sizes; (void)n_in; (void)out_size;
    const float* x  = (const float*)d_in[0];
    const float* Wq = (const float*)d_in[2];
    const float* Wk = (const float*)d_in[3];
    const float* Wv = (const float*)d_in[4];
    const float* Wo = (const float*)d_in[5];
    float* out = (float*)d_out;

    float *rawQKV, *cosT, *sinT;
    __nv_bfloat16 *xhi, *xlo, *Ohi, *Olo, *Qhi, *Qlo, *Khi, *Klo, *Vth, *Vtl;
    __nv_bfloat16 *Wch, *Wcl, *Woh, *Wol;
    cudaGetSymbolAddress((void**)&rawQKV, g_rawQKV);
    cudaGetSymbolAddress((void**)&cosT, g_cosT);
    cudaGetSymbolAddress((void**)&sinT, g_sinT);
    cudaGetSymbolAddress((void**)&xhi,  g_xhi);
    cudaGetSymbolAddress((void**)&xlo,  g_xlo);
    cudaGetSymbolAddress((void**)&Ohi,  g_Ohi);
    cudaGetSymbolAddress((void**)&Olo,  g_Olo);
    cudaGetSymbolAddress((void**)&Qhi,  g_Qhi);
    cudaGetSymbolAddress((void**)&Qlo,  g_Qlo);
    cudaGetSymbolAddress((void**)&Khi,  g_Khi);
    cudaGetSymbolAddress((void**)&Klo,  g_Klo);
    cudaGetSymbolAddress((void**)&Vth,  g_Vth);
    cudaGetSymbolAddress((void**)&Vtl,  g_Vtl);
    cudaGetSymbolAddress((void**)&Wch,  g_Wqkvt_h);
    cudaGetSymbolAddress((void**)&Wcl,  g_Wqkvt_l);
    cudaGetSymbolAddress((void**)&Woh,  g_Wot_h);
    cudaGetSymbolAddress((void**)&Wol,  g_Wot_l);

    cudaFuncSetAttribute(gemm_mma_kernel, cudaFuncAttributeMaxDynamicSharedMemorySize, GEMM_SMEM);
    cudaFuncSetAttribute(flash_mma_kernel, cudaFuncAttributeMaxDynamicSharedMemorySize, F_SMEM);

    // operand prep: x split; weights transposed+split into concat buffer
    split_kernel<<<((size_t)MROWS * DMODEL / 4) / 256, 256>>>(x, xhi, xlo);
    transpose_split_kernel<<<dim3(DMODEL/32, DMODEL/32), 256>>>(Wq, Wch, Wcl, DMODEL, DMODEL);
    transpose_split_kernel<<<dim3(KVW/32,    DMODEL/32), 256>>>(
        Wk, Wch + (size_t)DMODEL * DMODEL, Wcl + (size_t)DMODEL * DMODEL, DMODEL, KVW);
    transpose_split_kernel<<<dim3(KVW/32,    DMODEL/32), 256>>>(
        Wv, Wch + (size_t)(DMODEL + KVW) * DMODEL, Wcl + (size_t)(DMODEL + KVW) * DMODEL,
        DMODEL, KVW);
    transpose_split_kernel<<<dim3(DMODEL/32, DMODEL/32), 256>>>(Wo, Woh, Wol, DMODEL, DMODEL);
    rope_table_kernel<<<(SEQ * 64) / 256, 256>>>(cosT, sinT);

    // fused QKV projection: [4096, 6144]
    gemm_mma_kernel<<<dim3(NQKV/128, MROWS/128), 256, GEMM_SMEM>>>(
        xhi, xlo, Wch, Wcl, rawQKV, NQKV);

    // RoPE + relayout; V transpose-split
    rope_split_kernel<<<(BATCH * NHEADS * SEQ * 64) / 256, 256>>>(
        rawQKV, Qhi, Qlo, NHEADS, 0, cosT, sinT);
    rope_split_kernel<<<(BATCH * NKV    * SEQ * 64) / 256, 256>>>(
        rawQKV, Khi, Klo, NKV, DMODEL, cosT, sinT);
    vtrans_split_kernel<<<dim3(SEQ/32, HDIM/32, BATCH*NKV), 256>>>(rawQKV, Vth, Vtl);

    // register-P tensor-core causal flash attention
    flash_mma_kernel<<<dim3(SEQ/128, BATCH*NHEADS), 256, F_SMEM>>>(
        Qhi, Qlo, Khi, Klo, Vth, Vtl, Ohi, Olo);

    // output projection
    gemm_mma_kernel<<<dim3(DMODEL/128, MROWS/128), 256, GEMM_SMEM>>>(
        Ohi, Olo, Woh, Wol, out, DMODEL);
}

// round 11
// speedup vs baseline: 5.3118x; 1.0689x over previous
#include <cuda_runtime.h>
#include <cuda_bf16.h>
#include <math.h>
#include <stdint.h>

#define BATCH  2
#define SEQ    2048
#define DMODEL 4096
#define NHEADS 32
#define NKV    8
#define HDIM   128
#define MROWS  (BATCH*SEQ)        // 4096
#define KVW    (NKV*HDIM)         // 1024
#define NQKV   (DMODEL + 2*KVW)   // 6144

// ---------------- scratch (static device buffers; no cudaMalloc) -----------
__device__ __align__(256) float g_rawQKV[(size_t)MROWS * NQKV];   // [Q|K|V] fused proj

__device__ __align__(256) __nv_bfloat16 g_xhi[(size_t)MROWS * DMODEL];
__device__ __align__(256) __nv_bfloat16 g_xlo[(size_t)MROWS * DMODEL];
__device__ __align__(256) __nv_bfloat16 g_Ohi[(size_t)MROWS * DMODEL];
__device__ __align__(256) __nv_bfloat16 g_Olo[(size_t)MROWS * DMODEL];
__device__ __align__(256) __nv_bfloat16 g_Qhi[(size_t)MROWS * DMODEL];
__device__ __align__(256) __nv_bfloat16 g_Qlo[(size_t)MROWS * DMODEL];
__device__ __align__(256) __nv_bfloat16 g_Khi[(size_t)MROWS * KVW];
__device__ __align__(256) __nv_bfloat16 g_Klo[(size_t)MROWS * KVW];
__device__ __align__(256) __nv_bfloat16 g_Vth[(size_t)MROWS * KVW];
__device__ __align__(256) __nv_bfloat16 g_Vtl[(size_t)MROWS * KVW];
// concat transposed weights [Wq; Wk; Wv] = [NQKV, DMODEL] bf16 hi/lo
__device__ __align__(256) __nv_bfloat16 g_Wqkvt_h[(size_t)NQKV * DMODEL];
__device__ __align__(256) __nv_bfloat16 g_Wqkvt_l[(size_t)NQKV * DMODEL];
__device__ __align__(256) __nv_bfloat16 g_Wot_h[(size_t)DMODEL * DMODEL];
__device__ __align__(256) __nv_bfloat16 g_Wot_l[(size_t)DMODEL * DMODEL];
__device__ __align__(256) float g_cosT[SEQ * 64];
__device__ __align__(256) float g_sinT[SEQ * 64];

// ---------------- PTX helpers ----------------------------------------------
__device__ __forceinline__ uint32_t smem_u32(const void* p) {
    uint32_t a;
    asm("{ .reg .u64 t; cvta.to.shared.u64 t, %1; cvt.u32.u64 %0, t; }" : "=r"(a) : "l"(p));
    return a;
}

#define CP_ASYNC16(dst, src) \
    asm volatile("cp.async.cg.shared.global [%0], [%1], 16;" :: "r"(dst), "l"(src) : "memory")
#define CP_COMMIT() asm volatile("cp.async.commit_group;" ::: "memory")
#define CP_WAIT(n)  asm volatile("cp.async.wait_group %0;" :: "n"(n) : "memory")

#define LDSM_X4(r0, r1, r2, r3, addr) \
    asm volatile("ldmatrix.sync.aligned.m8n8.x4.shared.b16 {%0,%1,%2,%3}, [%4];" \
        : "=r"(r0), "=r"(r1), "=r"(r2), "=r"(r3) : "r"(addr))

#define MMA_BF16(d, a, b) \
    asm volatile("mma.sync.aligned.m16n8k16.row.col.f32.bf16.bf16.f32 " \
        "{%0,%1,%2,%3}, {%4,%5,%6,%7}, {%8,%9}, {%0,%1,%2,%3};" \
        : "+f"((d)[0]), "+f"((d)[1]), "+f"((d)[2]), "+f"((d)[3]) \
        : "r"((a)[0]), "r"((a)[1]), "r"((a)[2]), "r"((a)[3]), \
          "r"((b)[0]), "r"((b)[1]))

// chunk-tile addressing (validated R4): row r = 64B as four 16B groups,
// group g at ((g ^ ((r>>1)&3)) << 4)
#define TOFF(r, g) ((uint32_t)((r) * 64 + ((((g) ^ (((r) >> 1) & 3))) << 4)))

__device__ __forceinline__ void split_pack(float p0, float p1,
                                           uint32_t& hi, uint32_t& lo) {
    __nv_bfloat162 h{__float2bfloat16(p0), __float2bfloat16(p1)};
    hi = *reinterpret_cast<uint32_t*>(&h);
    __nv_bfloat162 l{__float2bfloat16(p0 - __bfloat162float(h.x)),
                     __float2bfloat16(p1 - __bfloat162float(h.y))};
    lo = *reinterpret_cast<uint32_t*>(&l);
}

// ---------------- conversion kernels ---------------------------------------
__global__ __launch_bounds__(256) void split_kernel(
    const float* __restrict__ X, __nv_bfloat16* __restrict__ H,
    __nv_bfloat16* __restrict__ L)
{
    size_t i = (size_t)blockIdx.x * 256 + threadIdx.x;
    float4 v = reinterpret_cast<const float4*>(X)[i];
    float a[4] = {v.x, v.y, v.z, v.w};
    __nv_bfloat162* H2 = reinterpret_cast<__nv_bfloat162*>(H);
    __nv_bfloat162* L2 = reinterpret_cast<__nv_bfloat162*>(L);
#pragma unroll
    for (int p = 0; p < 2; p++) {
        __nv_bfloat16 h0 = __float2bfloat16(a[p*2+0]);
        __nv_bfloat16 h1 = __float2bfloat16(a[p*2+1]);
        __nv_bfloat16 l0 = __float2bfloat16(a[p*2+0] - __bfloat162float(h0));
        __nv_bfloat16 l1 = __float2bfloat16(a[p*2+1] - __bfloat162float(h1));
        H2[i*2 + p] = __nv_bfloat162{h0, h1};
        L2[i*2 + p] = __nv_bfloat162{l0, l1};
    }
}

__global__ __launch_bounds__(256) void transpose_split_kernel(
    const float* __restrict__ W, __nv_bfloat16* __restrict__ Th,
    __nv_bfloat16* __restrict__ Tl, int K, int N)
{
    __shared__ float tile[32][33];
    int n0 = blockIdx.x * 32, k0 = blockIdx.y * 32;
    int tx = threadIdx.x & 31, ty = threadIdx.x >> 5;
#pragma unroll
    for (int j = 0; j < 32; j += 8)
        tile[ty + j][tx] = W[(size_t)(k0 + ty + j) * N + n0 + tx];
    __syncthreads();
#pragma unroll
    for (int j = 0; j < 32; j += 8) {
        float v = tile[tx][ty + j];
        __nv_bfloat16 h = __float2bfloat16(v);
        __nv_bfloat16 l = __float2bfloat16(v - __bfloat162float(h));
        size_t o = (size_t)(n0 + ty + j) * K + k0 + tx;
        Th[o] = h; Tl[o] = l;
    }
}

// V slice of rawQKV -> Vt hi/lo [B*KV, HDIM, SEQ]
__global__ __launch_bounds__(256) void vtrans_split_kernel(
    const float* __restrict__ raw, __nv_bfloat16* __restrict__ Th,
    __nv_bfloat16* __restrict__ Tl)
{
    __shared__ float tile[32][33];
    int s0 = blockIdx.x * 32, d0 = blockIdx.y * 32, bkv = blockIdx.z;
    int b = bkv >> 3, kvh = bkv & 7;
    int tx = threadIdx.x & 31, ty = threadIdx.x >> 5;
#pragma unroll
    for (int j = 0; j < 32; j += 8)
        tile[ty + j][tx] = raw[((size_t)(b * SEQ) + s0 + ty + j) * NQKV +
                               (DMODEL + KVW) + kvh * HDIM + d0 + tx];
    __syncthreads();
#pragma unroll
    for (int j = 0; j < 32; j += 8) {
        float v = tile[tx][ty + j];
        __nv_bfloat16 h = __float2bfloat16(v);
        __nv_bfloat16 l = __float2bfloat16(v - __bfloat162float(h));
        size_t o = ((size_t)bkv * HDIM + d0 + ty + j) * SEQ + s0 + tx;
        Th[o] = h; Tl[o] = l;
    }
}

// ---------------- RoPE table + apply ---------------------------------------
__global__ __launch_bounds__(256) void rope_table_kernel(
    float* __restrict__ cosT, float* __restrict__ sinT)
{
    int idx = blockIdx.x * 256 + threadIdx.x;
    int d2 = idx & 63, s = idx >> 6;
    float invf = expf(-(float)d2 * (9.210340371976184f / 64.0f));
    float ang  = (float)s * invf;
    double sv, cv;
    sincos((double)ang, &sv, &cv);
    cosT[idx] = (float)cv;
    sinT[idx] = (float)sv;
}

__global__ __launch_bounds__(256) void rope_split_kernel(
    const float* __restrict__ raw, __nv_bfloat16* __restrict__ Oh,
    __nv_bfloat16* __restrict__ Ol, int nheads, int colbase,
    const float* __restrict__ cosT, const float* __restrict__ sinT)
{
    int idx = blockIdx.x * 256 + threadIdx.x;
    int d2 = idx & 63;
    int t  = idx >> 6;
    int s  = t & (SEQ - 1);
    t >>= 11;
    int h = t % nheads;
    int b = t / nheads;
    if (b >= BATCH) return;

    const float* row = raw + ((size_t)(b * SEQ + s)) * NQKV + colbase + h * HDIM;
    float x0 = row[d2], x1 = row[d2 + 64];
    float c  = cosT[s * 64 + d2];
    float sn = sinT[s * 64 + d2];
    float o0 = x0 * c - x1 * sn;
    float o1 = x1 * c + x0 * sn;
    size_t ob = ((size_t)((b * nheads + h) * SEQ + s)) * HDIM;
    __nv_bfloat16 h0 = __float2bfloat16(o0);
    __nv_bfloat16 h1 = __float2bfloat16(o1);
    Oh[ob + d2]      = h0;
    Oh[ob + d2 + 64] = h1;
    Ol[ob + d2]      = __float2bfloat16(o0 - __bfloat162float(h0));
    Ol[ob + d2 + 64] = __float2bfloat16(o1 - __bfloat162float(h1));
}

// ---------------- mma.sync split-bf16 GEMM, 128x256 CTA, 3-stage -----------
// C[M,N] = A[M,4096] @ Bt[N,4096]^T.  8 warps (2 m x 4 n), warp tile 64x64.
// Per stage (48 KB): Ahi[8K] Alo[8K] Bhi[16K] Blo[16K]. 3 stages = 144 KB.
// AI = 48 FLOP/smem-byte -> MMA-bound (balance point is 32).
#define G_STAGE   49152
#define GEMM_SMEM (3 * G_STAGE)
#define G_NK      128            /* K=4096 / 32 */

__device__ __forceinline__ void load_stage(
    uint32_t st, int tid,
    const __nv_bfloat16* __restrict__ Ahi, const __nv_bfloat16* __restrict__ Alo,
    const __nv_bfloat16* __restrict__ Bhi, const __nv_bfloat16* __restrict__ Blo,
    int m0, int n0, int k0)
{
    // A: 2 mats x 128 rows x 4 groups = 1024 transfers; B: 2 x 256 x 4 = 2048
#pragma unroll
    for (int it = 0; it < 4; it++) {            // A hi/lo
        int id = tid + it * 256;
        int mat = id >> 9, w = id & 511;
        int r = w >> 2, g = w & 3;
        const __nv_bfloat16* src = (mat ? Alo : Ahi) + (size_t)(m0 + r) * 4096 + k0 + g * 8;
        CP_ASYNC16(st + mat * 8192 + TOFF(r, g), src);
    }
#pragma unroll
    for (int it = 0; it < 8; it++) {            // B hi/lo
        int id = tid + it * 256;
        int mat = id >> 10, w = id & 1023;
        int r = w >> 2, g = w & 3;
        const __nv_bfloat16* src = (mat ? Blo : Bhi) + (size_t)(n0 + r) * 4096 + k0 + g * 8;
        CP_ASYNC16(st + 16384 + mat * 16384 + TOFF(r, g), src);
    }
}

__global__ __launch_bounds__(256, 1) void gemm_mma_kernel(
    const __nv_bfloat16* __restrict__ Ahi, const __nv_bfloat16* __restrict__ Alo,
    const __nv_bfloat16* __restrict__ Bhi, const __nv_bfloat16* __restrict__ Blo,
    float* __restrict__ C, int N)
{
    extern __shared__ __align__(1024) char smem[];
    uint32_t sb = smem_u32(smem);
    const int tid = threadIdx.x;
    const int lane = tid & 31, wid = tid >> 5;
    const int warp_m = wid & 1, warp_n = wid >> 1;       // 2 x 4
    const int m0 = blockIdx.y * 128, n0 = blockIdx.x * 256;

    float acc[4][8][4];
#pragma unroll
    for (int mt = 0; mt < 4; mt++)
#pragma unroll
        for (int nt = 0; nt < 8; nt++)
#pragma unroll
            for (int q = 0; q < 4; q++) acc[mt][nt][q] = 0.f;

    load_stage(sb,           tid, Ahi, Alo, Bhi, Blo, m0, n0, 0);
    CP_COMMIT();
    load_stage(sb + G_STAGE, tid, Ahi, Alo, Bhi, Blo, m0, n0, 32);
    CP_COMMIT();

    const uint32_t aRowB = (uint32_t)(warp_m * 64 + (lane & 15));   // + mt*16
    const int aG = lane >> 4;
    const uint32_t bRowB = (uint32_t)(warp_n * 64 + (lane & 7) + ((lane >> 4) & 1) * 8);
    const int bG = (lane >> 3) & 1;

    int s_cur = 0, s_nxt = 2;
    for (int kb = 0; kb < G_NK; kb++) {
        if (kb < G_NK - 1) { CP_WAIT(1); } else { CP_WAIT(0); }
        __syncthreads();

        // prefetch chunk kb+2 into the stage freed at iteration kb-1
        if (kb + 2 < G_NK) {
            load_stage(sb + (uint32_t)s_nxt * G_STAGE, tid, Ahi, Alo, Bhi, Blo,
                       m0, n0, (kb + 2) * 32);
            CP_COMMIT();
        }

        const uint32_t st = sb + (uint32_t)s_cur * G_STAGE;
#pragma unroll
        for (int kk = 0; kk < 2; kk++) {
            uint32_t ah[4][4], al[4][4];
#pragma unroll
            for (int mt = 0; mt < 4; mt++) {
                uint32_t off = TOFF(aRowB + mt * 16, kk * 2 + aG);
                LDSM_X4(ah[mt][0], ah[mt][1], ah[mt][2], ah[mt][3], st + off);
                LDSM_X4(al[mt][0], al[mt][1], al[mt][2], al[mt][3], st + 8192 + off);
            }
#pragma unroll
            for (int p = 0; p < 4; p++) {
                uint32_t off = TOFF(bRowB + p * 16, kk * 2 + bG);
                uint32_t bh[4], bl[4];
                LDSM_X4(bh[0], bh[1], bh[2], bh[3], st + 16384 + off);
                LDSM_X4(bl[0], bl[1], bl[2], bl[3], st + 32768 + off);
#pragma unroll
                for (int mt = 0; mt < 4; mt++) {
                    MMA_BF16(acc[mt][2*p],     ah[mt], bh + 0);
                    MMA_BF16(acc[mt][2*p],     ah[mt], bl + 0);
                    MMA_BF16(acc[mt][2*p],     al[mt], bh + 0);
                    MMA_BF16(acc[mt][2*p + 1], ah[mt], bh + 2);
                    MMA_BF16(acc[mt][2*p + 1], ah[mt], bl + 2);
                    MMA_BF16(acc[mt][2*p + 1], al[mt], bh + 2);
                }
            }
        }
        s_cur = (s_cur == 2) ? 0 : s_cur + 1;
        s_nxt = (s_nxt == 2) ? 0 : s_nxt + 1;
    }

#pragma unroll
    for (int mt = 0; mt < 4; mt++) {
        int row = m0 + warp_m * 64 + mt * 16 + (lane >> 2);
#pragma unroll
        for (int nt = 0; nt < 8; nt++) {
            int col = n0 + warp_n * 64 + nt * 8 + (lane & 3) * 2;
            *reinterpret_cast<float2*>(C + (size_t)row * N + col) =
                float2{acc[mt][nt][0], acc[mt][nt][1]};
            *reinterpret_cast<float2*>(C + (size_t)(row + 8) * N + col) =
                float2{acc[mt][nt][2], acc[mt][nt][3]};
        }
    }
}

// ---------------- flash attention: register-P, 128q x 64kv (R8, validated) --
#define F_QHI  0
#define F_QLO  32768
#define F_STG  65536            /* + stage*65536 */
#define FS_KHI 0
#define FS_KLO 16384
#define FS_VHI 32768
#define FS_VLO 49152
#define F_SMEM (65536 + 2 * 65536)   /* 192 KB */

__device__ __forceinline__ void flash_load_stage(
    uint32_t st, int tid,
    const __nv_bfloat16* __restrict__ Kh, const __nv_bfloat16* __restrict__ Kl,
    const __nv_bfloat16* __restrict__ Vh, const __nv_bfloat16* __restrict__ Vl,
    int n0)
{
#pragma unroll
    for (int it = 0; it < 4; it++) {            // K hi/lo: 64 rows x 128 k
        int id = tid + it * 256;
        int r = id >> 4, cg = id & 15, kt = cg >> 2, g = cg & 3;
        uint32_t off = (uint32_t)(kt * 4096) + TOFF(r, g);
        CP_ASYNC16(st + FS_KHI + off, Kh + (size_t)(n0 + r) * 128 + kt * 32 + g * 8);
        CP_ASYNC16(st + FS_KLO + off, Kl + (size_t)(n0 + r) * 128 + kt * 32 + g * 8);
    }
#pragma unroll
    for (int it = 0; it < 4; it++) {            // Vt hi/lo: 128 rows x 64 kv
        int id = tid + it * 256;
        int r = id >> 3, cg = id & 7, kt = cg >> 2, g = cg & 3;
        uint32_t off = (uint32_t)(kt * 8192) + TOFF(r, g);
        CP_ASYNC16(st + FS_VHI + off, Vh + (size_t)r * SEQ + n0 + kt * 32 + g * 8);
        CP_ASYNC16(st + FS_VLO + off, Vl + (size_t)r * SEQ + n0 + kt * 32 + g * 8);
    }
}

__global__ __launch_bounds__(256, 1) void flash_mma_kernel(
    const __nv_bfloat16* __restrict__ Qh, const __nv_bfloat16* __restrict__ Ql,
    const __nv_bfloat16* __restrict__ Kh, const __nv_bfloat16* __restrict__ Kl,
    const __nv_bfloat16* __restrict__ Vth, const __nv_bfloat16* __restrict__ Vtl,
    __nv_bfloat16* __restrict__ Ohi, __nv_bfloat16* __restrict__ Olo)
{
    extern __shared__ __align__(1024) char fsm[];
    uint32_t sb = smem_u32(fsm);
    const int tid = threadIdx.x, lane = tid & 31, w = tid >> 5;
    const int mblk = gridDim.x - 1 - blockIdx.x;     // heavy CTAs first
    const int m0 = mblk * 128;
    const int bh = blockIdx.y, b = bh >> 5, h = bh & 31, kvh = h >> 2;
    const float scale = 0.08838834764831845f;

    const __nv_bfloat16* Qhp = Qh + ((size_t)(b * NHEADS + h) * SEQ + m0) * HDIM;
    const __nv_bfloat16* Qlp = Ql + ((size_t)(b * NHEADS + h) * SEQ + m0) * HDIM;
    const __nv_bfloat16* Khp = Kh + (size_t)(b * NKV + kvh) * SEQ * HDIM;
    const __nv_bfloat16* Klp = Kl + (size_t)(b * NKV + kvh) * SEQ * HDIM;
    const __nv_bfloat16* Vhp = Vth + (size_t)(b * NKV + kvh) * HDIM * SEQ;
    const __nv_bfloat16* Vlp = Vtl + (size_t)(b * NKV + kvh) * HDIM * SEQ;

    // Q resident: 128 rows x 128 k, hi/lo (grouped with stage 0)
#pragma unroll
    for (int it = 0; it < 8; it++) {
        int id = tid + it * 256;
        int r = id >> 4, cg = id & 15, kt = cg >> 2, g = cg & 3;
        uint32_t off = (uint32_t)(kt * 8192) + TOFF(r, g);
        CP_ASYNC16(sb + F_QHI + off, Qhp + (size_t)r * 128 + kt * 32 + g * 8);
        CP_ASYNC16(sb + F_QLO + off, Qlp + (size_t)r * 128 + kt * 32 + g * 8);
    }
    flash_load_stage(sb + F_STG, tid, Khp, Klp, Vhp, Vlp, 0);
    CP_COMMIT();

    float acc_o[16][4];
#pragma unroll
    for (int nf = 0; nf < 16; nf++)
#pragma unroll
        for (int q = 0; q < 4; q++) acc_o[nf][q] = 0.f;
    float mi0 = -INFINITY, mi1 = -INFINITY, li0 = 0.f, li1 = 0.f;

    const uint32_t aRow = (uint32_t)(w * 16 + (lane & 15));
    const int aG = lane >> 4;
    const uint32_t bLn = (uint32_t)((lane & 7) + ((lane >> 4) & 1) * 8);
    const int bG = (lane >> 3) & 1;
    const int r0 = w * 16 + (lane >> 2);             // local q row; +8 second

    const int nb = 2 * mblk + 2;
    for (int j = 0; j < nb; j++) {
        uint32_t st = sb + F_STG + (uint32_t)(j & 1) * 65536;
        if (j + 1 < nb) {
            flash_load_stage(sb + F_STG + (uint32_t)((j + 1) & 1) * 65536, tid,
                             Khp, Klp, Vhp, Vlp, (j + 1) * 64);
            CP_COMMIT();
            CP_WAIT(1);
        } else {
            CP_WAIT(0);
        }
        __syncthreads();

        // ---- S = Q @ K^T (3-product), warp-private 16x64 ----
        float s[8][4];
#pragma unroll
        for (int nt = 0; nt < 8; nt++)
#pragma unroll
            for (int q = 0; q < 4; q++) s[nt][q] = 0.f;

#pragma unroll
        for (int ks = 0; ks < 8; ks++) {
            int kt = ks >> 1, kh = ks & 1;
            uint32_t ah[4], al[4];
            uint32_t offA = (uint32_t)(kt * 8192) + TOFF(aRow, kh * 2 + aG);
            LDSM_X4(ah[0], ah[1], ah[2], ah[3], sb + F_QHI + offA);
            LDSM_X4(al[0], al[1], al[2], al[3], sb + F_QLO + offA);
#pragma unroll
            for (int np = 0; np < 4; np++) {
                uint32_t offB = (uint32_t)(kt * 4096) + TOFF(np * 16 + bLn, kh * 2 + bG);
                uint32_t kbh[4], kbl[4];
                LDSM_X4(kbh[0], kbh[1], kbh[2], kbh[3], st + FS_KHI + offB);
                LDSM_X4(kbl[0], kbl[1], kbl[2], kbl[3], st + FS_KLO + offB);
                MMA_BF16(s[2*np],     ah, kbh + 0);
                MMA_BF16(s[2*np],     ah, kbl + 0);
                MMA_BF16(s[2*np],     al, kbh + 0);
                MMA_BF16(s[2*np + 1], ah, kbh + 2);
                MMA_BF16(s[2*np + 1], ah, kbl + 2);
                MMA_BF16(s[2*np + 1], al, kbh + 2);
            }
        }

        // ---- scale + causal mask + register softmax ----
        const bool diag = (j >= nb - 2);
        const int qi0 = m0 + r0, qi1 = qi0 + 8;
        float pm0 = -INFINITY, pm1 = -INFINITY;
#pragma unroll
        for (int nt = 0; nt < 8; nt++) {
            int c0 = j * 64 + nt * 8 + (lane & 3) * 2;
            float v0 = s[nt][0] * scale, v1 = s[nt][1] * scale;
            float v2 = s[nt][2] * scale, v3 = s[nt][3] * scale;
            if (diag) {
                if (c0     > qi0) v0 = -INFINITY;
                if (c0 + 1 > qi0) v1 = -INFINITY;
                if (c0     > qi1) v2 = -INFINITY;
                if (c0 + 1 > qi1) v3 = -INFINITY;
            }
            s[nt][0] = v0; s[nt][1] = v1; s[nt][2] = v2; s[nt][3] = v3;
            pm0 = fmaxf(pm0, fmaxf(v0, v1));
            pm1 = fmaxf(pm1, fmaxf(v2, v3));
        }
        pm0 = fmaxf(pm0, __shfl_xor_sync(0xffffffffu, pm0, 1));
        pm0 = fmaxf(pm0, __shfl_xor_sync(0xffffffffu, pm0, 2));
        pm1 = fmaxf(pm1, __shfl_xor_sync(0xffffffffu, pm1, 1));
        pm1 = fmaxf(pm1, __shfl_xor_sync(0xffffffffu, pm1, 2));

        float mn0 = fmaxf(mi0, pm0), mn1 = fmaxf(mi1, pm1);
        float a0 = __expf(mi0 - mn0), a1 = __expf(mi1 - mn1);
        mi0 = mn0; mi1 = mn1;

        float ps0 = 0.f, ps1 = 0.f;
#pragma unroll
        for (int nt = 0; nt < 8; nt++) {
            float p0 = __expf(s[nt][0] - mn0);
            float p1 = __expf(s[nt][1] - mn0);
            float p2 = __expf(s[nt][2] - mn1);
            float p3 = __expf(s[nt][3] - mn1);
            s[nt][0] = p0; s[nt][1] = p1; s[nt][2] = p2; s[nt][3] = p3;
            ps0 += p0 + p1; ps1 += p2 + p3;
        }
        ps0 += __shfl_xor_sync(0xffffffffu, ps0, 1);
        ps0 += __shfl_xor_sync(0xffffffffu, ps0, 2);
        ps1 += __shfl_xor_sync(0xffffffffu, ps1, 1);
        ps1 += __shfl_xor_sync(0xffffffffu, ps1, 2);
        li0 = li0 * a0 + ps0;
        li1 = li1 * a1 + ps1;

#pragma unroll
        for (int nf = 0; nf < 16; nf++) {
            acc_o[nf][0] *= a0; acc_o[nf][1] *= a0;
            acc_o[nf][2] *= a1; acc_o[nf][3] *= a1;
        }

        // ---- O += P @ V  (P fragment-to-fragment in registers) ----
#pragma unroll
        for (int kt2 = 0; kt2 < 4; kt2++) {
            uint32_t pah[4], pal[4];
            split_pack(s[2*kt2][0],     s[2*kt2][1],     pah[0], pal[0]);
            split_pack(s[2*kt2][2],     s[2*kt2][3],     pah[1], pal[1]);
            split_pack(s[2*kt2 + 1][0], s[2*kt2 + 1][1], pah[2], pal[2]);
            split_pack(s[2*kt2 + 1][2], s[2*kt2 + 1][3], pah[3], pal[3]);
            int ktV = kt2 >> 1, khV = kt2 & 1;
#pragma unroll
            for (int np = 0; np < 8; np++) {
                uint32_t offV = (uint32_t)(ktV * 8192) + TOFF(np * 16 + bLn, khV * 2 + bG);
                uint32_t vh_[4], vl_[4];
                LDSM_X4(vh_[0], vh_[1], vh_[2], vh_[3], st + FS_VHI + offV);
                LDSM_X4(vl_[0], vl_[1], vl_[2], vl_[3], st + FS_VLO + offV);
                MMA_BF16(acc_o[2*np],     pah, vh_ + 0);
                MMA_BF16(acc_o[2*np],     pah, vl_ + 0);
                MMA_BF16(acc_o[2*np],     pal, vh_ + 0);
                MMA_BF16(acc_o[2*np + 1], pah, vh_ + 2);
                MMA_BF16(acc_o[2*np + 1], pah, vl_ + 2);
                MMA_BF16(acc_o[2*np + 1], pal, vh_ + 2);
            }
        }
        __syncthreads();   // protect stage buffers for refill
    }

    // ---- epilogue ----
    float inv0 = 1.f / li0, inv1 = 1.f / li1;
    size_t row0 = (size_t)(b * SEQ + m0 + r0) * DMODEL;
    size_t row1 = (size_t)(b * SEQ + m0 + r0 + 8) * DMODEL;
#pragma unroll
    for (int nf = 0; nf < 16; nf++) {
        int col = h * 128 + nf * 8 + (lane & 3) * 2;
        float o00 = acc_o[nf][0] * inv0, o01 = acc_o[nf][1] * inv0;
        float o10 = acc_o[nf][2] * inv1, o11 = acc_o[nf][3] * inv1;
        __nv_bfloat16 h00 = __float2bfloat16(o00), h01 = __float2bfloat16(o01);
        __nv_bfloat16 h10 = __float2bfloat16(o10), h11 = __float2bfloat16(o11);
        *(__nv_bfloat162*)(Ohi + row0 + col) = __nv_bfloat162{h00, h01};
        *(__nv_bfloat162*)(Ohi + row1 + col) = __nv_bfloat162{h10, h11};
        *(__nv_bfloat162*)(Olo + row0 + col) = __nv_bfloat162{
            __float2bfloat16(o00 - __bfloat162float(h00)),
            __float2bfloat16(o01 - __bfloat162float(h01))};
        *(__nv_bfloat162*)(Olo + row1 + col) = __nv_bfloat162{
            __float2bfloat16(o10 - __bfloat162float(h10)),
            __float2bfloat16(o11 - __bfloat162float(h11))};
    }
}

// ---------------- launch ----------------------------------------------------
extern "C" void kernel_launch(void* const* d_in, const int* in_sizes, int n_in,
                              void* d_out, int out_size)
{
    (void)in_sizes; (void)n_in; (void)out_size;
    const float* x  = (const float*)d_in[0];
    const float* Wq = (const float*)d_in[2];
    const float* Wk = (const float*)d_in[3];
    const float* Wv = (const float*)d_in[4];
    const float* Wo = (const float*)d_in[5];
    float* out = (float*)d_out;

    float *rawQKV, *cosT, *sinT;
    __nv_bfloat16 *xhi, *xlo, *Ohi, *Olo, *Qhi, *Qlo, *Khi, *Klo, *Vth, *Vtl;
    __nv_bfloat16 *Wch, *Wcl, *Woh, *Wol;
    cudaGetSymbolAddress((void**)&rawQKV, g_rawQKV);
    cudaGetSymbolAddress((void**)&cosT, g_cosT);
    cudaGetSymbolAddress((void**)&sinT, g_sinT);
    cudaGetSymbolAddress((void**)&xhi,  g_xhi);
    cudaGetSymbolAddress((void**)&xlo,  g_xlo);
    cudaGetSymbolAddress((void**)&Ohi,  g_Ohi);
    cudaGetSymbolAddress((void**)&Olo,  g_Olo);
    cudaGetSymbolAddress((void**)&Qhi,  g_Qhi);
    cudaGetSymbolAddress((void**)&Qlo,  g_Qlo);
    cudaGetSymbolAddress((void**)&Khi,  g_Khi);
    cudaGetSymbolAddress((void**)&Klo,  g_Klo);
    cudaGetSymbolAddress((void**)&Vth,  g_Vth);
    cudaGetSymbolAddress((void**)&Vtl,  g_Vtl);
    cudaGetSymbolAddress((void**)&Wch,  g_Wqkvt_h);
    cudaGetSymbolAddress((void**)&Wcl,  g_Wqkvt_l);
    cudaGetSymbolAddress((void**)&Woh,  g_Wot_h);
    cudaGetSymbolAddress((void**)&Wol,  g_Wot_l);

    cudaFuncSetAttribute(gemm_mma_kernel, cudaFuncAttributeMaxDynamicSharedMemorySize, GEMM_SMEM);
    cudaFuncSetAttribute(flash_mma_kernel, cudaFuncAttributeMaxDynamicSharedMemorySize, F_SMEM);

    // operand prep: x split; weights transposed+split into concat buffer
    split_kernel<<<((size_t)MROWS * DMODEL / 4) / 256, 256>>>(x, xhi, xlo);
    transpose_split_kernel<<<dim3(DMODEL/32, DMODEL/32), 256>>>(Wq, Wch, Wcl, DMODEL, DMODEL);
    transpose_split_kernel<<<dim3(KVW/32,    DMODEL/32), 256>>>(
        Wk, Wch + (size_t)DMODEL * DMODEL, Wcl + (size_t)DMODEL * DMODEL, DMODEL, KVW);
    transpose_split_kernel<<<dim3(KVW/32,    DMODEL/32), 256>>>(
        Wv, Wch + (size_t)(DMODEL + KVW) * DMODEL, Wcl + (size_t)(DMODEL + KVW) * DMODEL,
        DMODEL, KVW);
    transpose_split_kernel<<<dim3(DMODEL/32, DMODEL/32), 256>>>(Wo, Woh, Wol, DMODEL, DMODEL);
    rope_table_kernel<<<(SEQ * 64) / 256, 256>>>(cosT, sinT);

    // fused QKV projection: [4096, 6144]
    gemm_mma_kernel<<<dim3(NQKV/256, MROWS/128), 256, GEMM_SMEM>>>(
        xhi, xlo, Wch, Wcl, rawQKV, NQKV);

    // RoPE + relayout; V transpose-split
    rope_split_kernel<<<(BATCH * NHEADS * SEQ * 64) / 256, 256>>>(
        rawQKV, Qhi, Qlo, NHEADS, 0, cosT, sinT);
    rope_split_kernel<<<(BATCH * NKV    * SEQ * 64) / 256, 256>>>(
        rawQKV, Khi, Klo, NKV, DMODEL, cosT, sinT);
    vtrans_split_kernel<<<dim3(SEQ/32, HDIM/32, BATCH*NKV), 256>>>(rawQKV, Vth, Vtl);

    // register-P tensor-core causal flash attention
    flash_mma_kernel<<<dim3(SEQ/128, BATCH*NHEADS), 256, F_SMEM>>>(
        Qhi, Qlo, Khi, Klo, Vth, Vtl, Ohi, Olo);

    // output projection
    gemm_mma_kernel<<<dim3(DMODEL/256, MROWS/128), 256, GEMM_SMEM>>>(
        Ohi, Olo, Woh, Wol, out, DMODEL);
}